// round 3
// baseline (speedup 1.0000x reference)
#include <cuda_runtime.h>
#include <cstdint>
#include <cstddef>

// Problem constants
#define BATCH 2
#define SEQ   2048
#define HID   1024
#define NH    16
#define HD    64
#define BH    (BATCH*NH)            // 32
#define MROWS (BATCH*SEQ)           // 4096
#define SCALE_ATT 0.125f            // 1/sqrt(64)
#define OUT_ELEMS ((size_t)BATCH*SEQ*HID)          // 4,194,304
#define ATTN_ELEMS ((size_t)BH*SEQ*SEQ)            // 134,217,728

// ---------------- device scratch (no allocs allowed) ----------------
__device__ float g_T[2][64*64];                 // 0: T for Q/K, 1: T for V
__device__ float g_Wt[3][HID*HID];              // transformed Wq,Wk,Wv
__device__ float g_bt[3][HID];
__device__ float g_QKV[3][(size_t)BH*SEQ*HD];   // Qq,Kq,Vq  [B,NH,S,D]
__device__ float g_ctx[(size_t)MROWS*HID];      // context   [B,S,HID]

// ---------------- 1) build the 64x64 composite transforms ----------------
// Row-vector convention: y = x * T, T[i*64+j] = (F(e_i))_j
__global__ void build_T_kernel(const float* __restrict__ ent_w,  // [4,16,16]
                               const float* __restrict__ ent_s,  // [4]
                               const float* __restrict__ sup_w,  // [8,64]
                               const float* __restrict__ sup_c)  // [8]
{
    int t = threadIdx.x;
    if (t >= 128) return;
    int v = t >> 6;      // 0: QK path, 1: V path
    int i = t & 63;

    float x[64];
#pragma unroll
    for (int j = 0; j < 64; ++j) x[j] = (j == i) ? 1.0f : 0.0f;

    // entangle: per 16-group p: w = x_p @ ent_w[p]
    float w[64];
    for (int p = 0; p < 4; ++p)
        for (int j = 0; j < 16; ++j) {
            float acc = 0.f;
            for (int ii = 0; ii < 16; ++ii)
                acc += x[p*16 + ii] * ent_w[p*256 + ii*16 + j];
            w[p*16 + j] = acc;
        }
    // CNOT perm (swap elems 2<->3 per 4-group), scale by ent_s[p]
    for (int g = 0; g < 16; ++g) {
        float sc = ent_s[g >> 2];
        x[4*g+0] = w[4*g+0]*sc;
        x[4*g+1] = w[4*g+1]*sc;
        x[4*g+2] = w[4*g+3]*sc;
        x[4*g+3] = w[4*g+2]*sc;
    }
    // superpose: hadamard then elementwise * sum_n sup_c[n]*sup_w[n]
    const float R = 0.70710678118654752440f;
    for (int pr = 0; pr < 32; ++pr) {
        float a = x[2*pr], b = x[2*pr+1];
        x[2*pr]   = (a + b) * R;
        x[2*pr+1] = (a - b) * R;
    }
    for (int d = 0; d < 64; ++d) {
        float s = 0.f;
        for (int n = 0; n < 8; ++n) s += sup_c[n] * sup_w[n*64 + d];
        x[d] *= s;
    }
    if (v == 0) { // final hadamard (Q,K)
        for (int pr = 0; pr < 32; ++pr) {
            float a = x[2*pr], b = x[2*pr+1];
            x[2*pr]   = (a + b) * R;
            x[2*pr+1] = (a - b) * R;
        }
    } else {      // final CNOT perm (V)
        for (int g = 0; g < 16; ++g) {
            float a = x[4*g+2];
            x[4*g+2] = x[4*g+3];
            x[4*g+3] = a;
        }
    }
#pragma unroll
    for (int j = 0; j < 64; ++j) g_T[v][i*64 + j] = x[j];
}

// ---------------- 2) fold T into projection weights ----------------
// W'[m,k] = sum_i T[i, m%64] * W[(m/64)*64+i, k];  b'[m] similarly
__global__ void transform_W_kernel(const float* __restrict__ W,
                                   const float* __restrict__ bvec,
                                   int mat)
{
    const float* T = g_T[(mat == 2) ? 1 : 0];
    int k = blockIdx.x*16 + threadIdx.x;
    int m = blockIdx.y*16 + threadIdx.y;
    int h = m >> 6, ml = m & 63;
    float acc = 0.f;
#pragma unroll 8
    for (int i = 0; i < 64; ++i)
        acc += T[i*64 + ml] * W[((h<<6) + i)*HID + k];
    g_Wt[mat][(size_t)m*HID + k] = acc;
    if (blockIdx.x == 0 && threadIdx.x == 0) {
        float ab = 0.f;
        for (int i = 0; i < 64; ++i) ab += T[i*64 + ml] * bvec[(h<<6) + i];
        g_bt[mat][m] = ab;
    }
}

// ================= big-tile fp32 GEMMs: 128x128 tile, 8x8 microtile =======
#define PADM 132   // 128 + 4, keeps 16B alignment for float4 smem reads

// ---------------- 3) projection GEMM: C = A * W'^T + b', scatter [B,NH,S,D] --
// grid (HID/128, MROWS/128), 256 threads
__global__ void proj_gemm_kernel(const float* __restrict__ A, int mat)
{
    __shared__ float As[16][PADM];
    __shared__ float Bs[16][PADM];
    const float* __restrict__ Wm = g_Wt[mat];
    const float* __restrict__ bm = g_bt[mat];
    float* __restrict__ Cdst = g_QKV[mat];

    const int m0 = blockIdx.y * 128;
    const int n0 = blockIdx.x * 128;
    const int tid = threadIdx.x;
    const int tx = tid & 15, ty = tid >> 4;

    float acc[8][8] = {};
    for (int k0 = 0; k0 < HID; k0 += 16) {
        // load A tile 128x16 and B tile 128x16, both transposed into smem
#pragma unroll
        for (int l = 0; l < 2; ++l) {
            int idx = tid + l*256;
            int r = idx >> 2, c4 = (idx & 3) * 4;
            float4 av = *reinterpret_cast<const float4*>(&A[(size_t)(m0 + r)*HID + k0 + c4]);
            As[c4+0][r] = av.x; As[c4+1][r] = av.y; As[c4+2][r] = av.z; As[c4+3][r] = av.w;
            float4 bv = *reinterpret_cast<const float4*>(&Wm[(size_t)(n0 + r)*HID + k0 + c4]);
            Bs[c4+0][r] = bv.x; Bs[c4+1][r] = bv.y; Bs[c4+2][r] = bv.z; Bs[c4+3][r] = bv.w;
        }
        __syncthreads();
#pragma unroll
        for (int kk = 0; kk < 16; ++kk) {
            float4 a0 = *reinterpret_cast<const float4*>(&As[kk][ty*8]);
            float4 a1 = *reinterpret_cast<const float4*>(&As[kk][ty*8+4]);
            float4 b0 = *reinterpret_cast<const float4*>(&Bs[kk][tx*8]);
            float4 b1 = *reinterpret_cast<const float4*>(&Bs[kk][tx*8+4]);
            float a[8] = {a0.x,a0.y,a0.z,a0.w,a1.x,a1.y,a1.z,a1.w};
            float b[8] = {b0.x,b0.y,b0.z,b0.w,b1.x,b1.y,b1.z,b1.w};
#pragma unroll
            for (int ii = 0; ii < 8; ++ii)
#pragma unroll
                for (int jj = 0; jj < 8; ++jj)
                    acc[ii][jj] += a[ii]*b[jj];
        }
        __syncthreads();
    }
#pragma unroll
    for (int ii = 0; ii < 8; ++ii) {
        int m = m0 + ty*8 + ii;          // = b*SEQ + s
        int bi = m >> 11, s = m & 2047;
#pragma unroll
        for (int jj = 0; jj < 8; ++jj) {
            int n = n0 + tx*8 + jj;      // = h*64 + d
            int h = n >> 6, d = n & 63;
            Cdst[(((size_t)bi*NH + h)*SEQ + s)*HD + d] = acc[ii][jj] + bm[n];
        }
    }
}

// ---------------- 4) scores: attn_raw = scale * Q K^T per (b,h) ----------------
// grid (SEQ/128, SEQ/128, BH), 256 threads; K=64 in two 32-chunks
__global__ void scores_gemm_kernel(float* __restrict__ attn)
{
    __shared__ float As[32][PADM];
    __shared__ float Bs[32][PADM];
    const int z = blockIdx.z;
    const float* __restrict__ Az = g_QKV[0] + (size_t)z*SEQ*HD;
    const float* __restrict__ Bz = g_QKV[1] + (size_t)z*SEQ*HD;
    float* __restrict__ Cz = attn + (size_t)z*SEQ*SEQ;

    const int m0 = blockIdx.y * 128;
    const int n0 = blockIdx.x * 128;
    const int tid = threadIdx.x;
    const int tx = tid & 15, ty = tid >> 4;

    float acc[8][8] = {};
    for (int k0 = 0; k0 < HD; k0 += 32) {
#pragma unroll
        for (int l = 0; l < 4; ++l) {
            int idx = tid + l*256;
            int r = idx >> 3, c4 = (idx & 7) * 4;   // 128 rows x 8 float4
            float4 av = *reinterpret_cast<const float4*>(&Az[(size_t)(m0 + r)*HD + k0 + c4]);
            As[c4+0][r] = av.x; As[c4+1][r] = av.y; As[c4+2][r] = av.z; As[c4+3][r] = av.w;
            float4 bv = *reinterpret_cast<const float4*>(&Bz[(size_t)(n0 + r)*HD + k0 + c4]);
            Bs[c4+0][r] = bv.x; Bs[c4+1][r] = bv.y; Bs[c4+2][r] = bv.z; Bs[c4+3][r] = bv.w;
        }
        __syncthreads();
#pragma unroll
        for (int kk = 0; kk < 32; ++kk) {
            float4 a0 = *reinterpret_cast<const float4*>(&As[kk][ty*8]);
            float4 a1 = *reinterpret_cast<const float4*>(&As[kk][ty*8+4]);
            float4 b0 = *reinterpret_cast<const float4*>(&Bs[kk][tx*8]);
            float4 b1 = *reinterpret_cast<const float4*>(&Bs[kk][tx*8+4]);
            float a[8] = {a0.x,a0.y,a0.z,a0.w,a1.x,a1.y,a1.z,a1.w};
            float b[8] = {b0.x,b0.y,b0.z,b0.w,b1.x,b1.y,b1.z,b1.w};
#pragma unroll
            for (int ii = 0; ii < 8; ++ii)
#pragma unroll
                for (int jj = 0; jj < 8; ++jj)
                    acc[ii][jj] += a[ii]*b[jj];
        }
        __syncthreads();
    }
#pragma unroll
    for (int ii = 0; ii < 8; ++ii) {
        size_t rowb = (size_t)(m0 + ty*8 + ii)*SEQ + n0 + tx*8;
#pragma unroll
        for (int jj = 0; jj < 8; ++jj)
            Cz[rowb + jj] = acc[ii][jj]*SCALE_ATT;
    }
}

// ---------------- 5) softmax over each row (in place) ----------------
__global__ void softmax_kernel(float* __restrict__ attn)
{
    __shared__ float row[SEQ];
    __shared__ float red[256];
    const size_t base = (size_t)blockIdx.x * SEQ;
    const int t = threadIdx.x;

    float m = -3.0e38f;
#pragma unroll
    for (int i = 0; i < 8; ++i) {
        float v = attn[base + t + i*256];
        row[t + i*256] = v;
        m = fmaxf(m, v);
    }
    red[t] = m; __syncthreads();
    for (int o = 128; o > 0; o >>= 1) {
        if (t < o) red[t] = fmaxf(red[t], red[t + o]);
        __syncthreads();
    }
    const float mx = red[0];
    __syncthreads();

    float ssum = 0.f;
#pragma unroll
    for (int i = 0; i < 8; ++i) {
        float e = __expf(row[t + i*256] - mx);
        row[t + i*256] = e;
        ssum += e;
    }
    red[t] = ssum; __syncthreads();
    for (int o = 128; o > 0; o >>= 1) {
        if (t < o) red[t] += red[t + o];
        __syncthreads();
    }
    const float inv = 1.0f / red[0];
#pragma unroll
    for (int i = 0; i < 8; ++i)
        attn[base + t + i*256] = row[t + i*256] * inv;
}

// ---------------- 6) context = attn @ V, written to [B,S,HID] ----------------
// grid (1, SEQ/128, BH), 256 threads; M=128, N=64, K=2048; microtile 8x4
__global__ void ctx_gemm_kernel(const float* __restrict__ attn)
{
    __shared__ float As[16][PADM];
    __shared__ float Bs[16][64];
    const int z = blockIdx.z;
    const float* __restrict__ Az = attn + (size_t)z*SEQ*SEQ;
    const float* __restrict__ Bz = g_QKV[2] + (size_t)z*SEQ*HD;

    const int m0 = blockIdx.y * 128;
    const int tid = threadIdx.x;
    const int tx = tid & 15, ty = tid >> 4;

    float acc[8][4] = {};
    for (int k0 = 0; k0 < SEQ; k0 += 16) {
#pragma unroll
        for (int l = 0; l < 2; ++l) {
            int idx = tid + l*256;
            int r = idx >> 2, c4 = (idx & 3) * 4;   // 128 rows x 4 float4
            float4 av = *reinterpret_cast<const float4*>(&Az[(size_t)(m0 + r)*SEQ + k0 + c4]);
            As[c4+0][r] = av.x; As[c4+1][r] = av.y; As[c4+2][r] = av.z; As[c4+3][r] = av.w;
        }
        {
            int r = tid >> 4, c4 = (tid & 15) * 4;  // 16 rows x 16 float4
            *reinterpret_cast<float4*>(&Bs[r][c4]) =
                *reinterpret_cast<const float4*>(&Bz[(size_t)(k0 + r)*HD + c4]);
        }
        __syncthreads();
#pragma unroll
        for (int kk = 0; kk < 16; ++kk) {
            float4 a0 = *reinterpret_cast<const float4*>(&As[kk][ty*8]);
            float4 a1 = *reinterpret_cast<const float4*>(&As[kk][ty*8+4]);
            float4 b0 = *reinterpret_cast<const float4*>(&Bs[kk][tx*4]);
            float a[8] = {a0.x,a0.y,a0.z,a0.w,a1.x,a1.y,a1.z,a1.w};
            float b[4] = {b0.x,b0.y,b0.z,b0.w};
#pragma unroll
            for (int ii = 0; ii < 8; ++ii)
#pragma unroll
                for (int jj = 0; jj < 4; ++jj)
                    acc[ii][jj] += a[ii]*b[jj];
        }
        __syncthreads();
    }
    const int bi = z >> 4, h = z & 15;
#pragma unroll
    for (int ii = 0; ii < 8; ++ii) {
        int q = m0 + ty*8 + ii;
#pragma unroll
        for (int jj = 0; jj < 4; ++jj) {
            int d = tx*4 + jj;
            g_ctx[((size_t)bi*SEQ + q)*HID + (h<<6) + d] = acc[ii][jj];
        }
    }
}

// ---------------- 7) output = ctx @ Wo^T + bo ----------------
// grid (HID/128, MROWS/128), 256 threads
__global__ void out_gemm_kernel(const float* __restrict__ Wo,
                                const float* __restrict__ bo,
                                float* __restrict__ out)
{
    __shared__ float As[16][PADM];
    __shared__ float Bs[16][PADM];
    const int m0 = blockIdx.y * 128;
    const int n0 = blockIdx.x * 128;
    const int tid = threadIdx.x;
    const int tx = tid & 15, ty = tid >> 4;

    float acc[8][8] = {};
    for (int k0 = 0; k0 < HID; k0 += 16) {
#pragma unroll
        for (int l = 0; l < 2; ++l) {
            int idx = tid + l*256;
            int r = idx >> 2, c4 = (idx & 3) * 4;
            float4 av = *reinterpret_cast<const float4*>(&g_ctx[(size_t)(m0 + r)*HID + k0 + c4]);
            As[c4+0][r] = av.x; As[c4+1][r] = av.y; As[c4+2][r] = av.z; As[c4+3][r] = av.w;
            float4 bv = *reinterpret_cast<const float4*>(&Wo[(size_t)(n0 + r)*HID + k0 + c4]);
            Bs[c4+0][r] = bv.x; Bs[c4+1][r] = bv.y; Bs[c4+2][r] = bv.z; Bs[c4+3][r] = bv.w;
        }
        __syncthreads();
#pragma unroll
        for (int kk = 0; kk < 16; ++kk) {
            float4 a0 = *reinterpret_cast<const float4*>(&As[kk][ty*8]);
            float4 a1 = *reinterpret_cast<const float4*>(&As[kk][ty*8+4]);
            float4 b0 = *reinterpret_cast<const float4*>(&Bs[kk][tx*8]);
            float4 b1 = *reinterpret_cast<const float4*>(&Bs[kk][tx*8+4]);
            float a[8] = {a0.x,a0.y,a0.z,a0.w,a1.x,a1.y,a1.z,a1.w};
            float b[8] = {b0.x,b0.y,b0.z,b0.w,b1.x,b1.y,b1.z,b1.w};
#pragma unroll
            for (int ii = 0; ii < 8; ++ii)
#pragma unroll
                for (int jj = 0; jj < 8; ++jj)
                    acc[ii][jj] += a[ii]*b[jj];
        }
        __syncthreads();
    }
#pragma unroll
    for (int ii = 0; ii < 8; ++ii)
#pragma unroll
        for (int jj = 0; jj < 8; ++jj) {
            int m = m0 + ty*8 + ii, n = n0 + tx*8 + jj;
            out[(size_t)m*HID + n] = acc[ii][jj] + bo[n];
        }
}

// ---------------- launch ----------------
extern "C" void kernel_launch(void* const* d_in, const int* in_sizes, int n_in,
                              void* d_out, int out_size)
{
    const float* query = (const float*)d_in[0];
    const float* key   = (const float*)d_in[1];
    const float* value = (const float*)d_in[2];
    const float* Wq = (const float*)d_in[3];  const float* bq = (const float*)d_in[4];
    const float* Wk = (const float*)d_in[5];  const float* bk = (const float*)d_in[6];
    const float* Wv = (const float*)d_in[7];  const float* bv = (const float*)d_in[8];
    const float* Wo = (const float*)d_in[9];  const float* bo = (const float*)d_in[10];
    const float* ent_w = (const float*)d_in[11];
    const float* ent_s = (const float*)d_in[12];
    const float* sup_w = (const float*)d_in[13];
    const float* sup_c = (const float*)d_in[14];

    float* out  = (float*)d_out;                 // [B,S,HID]
    float* attn = (float*)d_out + OUT_ELEMS;     // [B,NH,S,S]
    (void)in_sizes; (void)n_in; (void)out_size;

    // 1) composite 64x64 transforms
    build_T_kernel<<<1, 128>>>(ent_w, ent_s, sup_w, sup_c);

    // 2) fold transforms into projection weights
    dim3 tgrid(HID/16, HID/16);
    dim3 tblk(16, 16);
    transform_W_kernel<<<tgrid, tblk>>>(Wq, bq, 0);
    transform_W_kernel<<<tgrid, tblk>>>(Wk, bk, 1);
    transform_W_kernel<<<tgrid, tblk>>>(Wv, bv, 2);

    // 3) projections
    dim3 pgrid(HID/128, MROWS/128);
    proj_gemm_kernel<<<pgrid, 256>>>(query, 0);
    proj_gemm_kernel<<<pgrid, 256>>>(key,   1);
    proj_gemm_kernel<<<pgrid, 256>>>(value, 2);

    // 4) raw scores into attn buffer
    dim3 sgrid(SEQ/128, SEQ/128, BH);
    scores_gemm_kernel<<<sgrid, 256>>>(attn);

    // 5) softmax in place
    softmax_kernel<<<BH*SEQ, 256>>>(attn);

    // 6) context
    dim3 cgrid(1, SEQ/128, BH);
    ctx_gemm_kernel<<<cgrid, 256>>>(attn);

    // 7) output projection
    dim3 ogrid(HID/128, MROWS/128);
    out_gemm_kernel<<<ogrid, 256>>>(Wo, bo, out);
}

// round 5
// speedup vs baseline: 3.4144x; 3.4144x over previous
#include <cuda_runtime.h>
#include <cstdint>
#include <cstddef>

// Problem constants
#define BATCH 2
#define SEQ   2048
#define HID   1024
#define NH    16
#define HD    64
#define BH    (BATCH*NH)            // 32
#define MROWS (BATCH*SEQ)           // 4096
#define SCALE_ATT 0.125f            // 1/sqrt(64)
#define OUT_ELEMS ((size_t)BATCH*SEQ*HID)          // 4,194,304

// ---------------- device scratch (no allocs allowed) ----------------
__device__ float g_T[2][64*64];                 // 0: T for Q/K, 1: T for V
__device__ float g_Wt[3][HID*HID];              // transformed Wq,Wk,Wv
__device__ float g_bt[3][HID];
__device__ float g_QKV[3][(size_t)BH*SEQ*HD];   // Qq,Kq,Vq  [B,NH,S,D]
__device__ float g_Vt[(size_t)BH*HD*SEQ];       // V transposed [bh][d][s]
__device__ float g_ctx[(size_t)MROWS*HID];      // context   [B,S,HID]

// ---------------- tf32 mma helpers ----------------
__device__ __forceinline__ uint32_t f2tf32(float f) {
    uint32_t r;
    asm("cvt.rna.tf32.f32 %0, %1;" : "=r"(r) : "f"(f));
    return r;
}
__device__ __forceinline__ void mma_tf32(float c[4],
                                         uint32_t a0, uint32_t a1, uint32_t a2, uint32_t a3,
                                         uint32_t b0, uint32_t b1) {
    asm volatile(
        "mma.sync.aligned.m16n8k8.row.col.f32.tf32.tf32.f32 "
        "{%0,%1,%2,%3}, {%4,%5,%6,%7}, {%8,%9}, {%0,%1,%2,%3};"
        : "+f"(c[0]), "+f"(c[1]), "+f"(c[2]), "+f"(c[3])
        : "r"(a0), "r"(a1), "r"(a2), "r"(a3), "r"(b0), "r"(b1));
}

// ---------------- 1) build the 64x64 composite transforms ----------------
__global__ void build_T_kernel(const float* __restrict__ ent_w,  // [4,16,16]
                               const float* __restrict__ ent_s,  // [4]
                               const float* __restrict__ sup_w,  // [8,64]
                               const float* __restrict__ sup_c)  // [8]
{
    int t = threadIdx.x;
    if (t >= 128) return;
    int v = t >> 6;      // 0: QK path, 1: V path
    int i = t & 63;

    float x[64];
#pragma unroll
    for (int j = 0; j < 64; ++j) x[j] = (j == i) ? 1.0f : 0.0f;

    float w[64];
    for (int p = 0; p < 4; ++p)
        for (int j = 0; j < 16; ++j) {
            float acc = 0.f;
            for (int ii = 0; ii < 16; ++ii)
                acc += x[p*16 + ii] * ent_w[p*256 + ii*16 + j];
            w[p*16 + j] = acc;
        }
    for (int g = 0; g < 16; ++g) {
        float sc = ent_s[g >> 2];
        x[4*g+0] = w[4*g+0]*sc;
        x[4*g+1] = w[4*g+1]*sc;
        x[4*g+2] = w[4*g+3]*sc;
        x[4*g+3] = w[4*g+2]*sc;
    }
    const float R = 0.70710678118654752440f;
    for (int pr = 0; pr < 32; ++pr) {
        float a = x[2*pr], b = x[2*pr+1];
        x[2*pr]   = (a + b) * R;
        x[2*pr+1] = (a - b) * R;
    }
    for (int d = 0; d < 64; ++d) {
        float s = 0.f;
        for (int n = 0; n < 8; ++n) s += sup_c[n] * sup_w[n*64 + d];
        x[d] *= s;
    }
    if (v == 0) {
        for (int pr = 0; pr < 32; ++pr) {
            float a = x[2*pr], b = x[2*pr+1];
            x[2*pr]   = (a + b) * R;
            x[2*pr+1] = (a - b) * R;
        }
    } else {
        for (int g = 0; g < 16; ++g) {
            float a = x[4*g+2];
            x[4*g+2] = x[4*g+3];
            x[4*g+3] = a;
        }
    }
#pragma unroll
    for (int j = 0; j < 64; ++j) g_T[v][i*64 + j] = x[j];
}

// ---------------- 2) fold T into projection weights (smem-tiled) ----------
// W'[h*64+ml, k] = sum_i T[i,ml] * W[h*64+i, k]
// grid (16 kblocks, 16 heads), 256 threads
__global__ void transform_W_kernel(const float* __restrict__ W,
                                   const float* __restrict__ bvec,
                                   int mat)
{
    __shared__ float Ts[64][65];
    __shared__ float Ws[64][65];
    const float* __restrict__ T = g_T[(mat == 2) ? 1 : 0];
    const int head = blockIdx.y;
    const int k0 = blockIdx.x * 64;
    const int tid = threadIdx.x;

#pragma unroll
    for (int l = 0; l < 16; ++l) {
        int idx = tid + l*256;
        int i = idx >> 6, c = idx & 63;
        Ts[i][c] = T[idx];
        Ws[i][c] = W[(size_t)(head*64 + i)*HID + k0 + c];
    }
    __syncthreads();

    const int k = tid & 63, g = tid >> 6;   // g in 0..3, 16 ml values each
    float acc[16] = {};
    for (int i = 0; i < 64; ++i) {
        float wv = Ws[i][k];
#pragma unroll
        for (int j = 0; j < 16; ++j)
            acc[j] += Ts[i][g*16 + j] * wv;
    }
#pragma unroll
    for (int j = 0; j < 16; ++j)
        g_Wt[mat][(size_t)(head*64 + g*16 + j)*HID + k0 + k] = acc[j];

    if (blockIdx.x == 0 && tid < 64) {
        float ab = 0.f;
        for (int i = 0; i < 64; ++i)
            ab += Ts[i][tid] * bvec[head*64 + i];
        g_bt[mat][head*64 + tid] = ab;
    }
}

// ============== tf32 MMA GEMMs ==============
// CTA tile 128x128 (proj/scores/out) or 128x64 (ctx). smem row-major [rows][20],
// tf32-converted at staging. warp layout 2(M)x4(N), warp tile 64x32.

// ---------------- 3) projection: C = A * W'^T + b', scatter [B,NH,S,D] ------
// grid (HID/128=8, MROWS/128=32), 256 threads
__global__ void proj_mma_kernel(const float* __restrict__ A, int mat)
{
    __shared__ uint32_t As[128][20];
    __shared__ uint32_t Bs[128][20];
    const float* __restrict__ Wm = g_Wt[mat];
    const float* __restrict__ bm = g_bt[mat];
    float* __restrict__ Cdst = g_QKV[mat];

    const int m0 = blockIdx.y * 128, n0 = blockIdx.x * 128;
    const int tid = threadIdx.x, lane = tid & 31, warp = tid >> 5;
    const int wm = (warp & 1) * 64, wn = (warp >> 1) * 32;

    float c[4][4][4];
#pragma unroll
    for (int a = 0; a < 4; ++a)
#pragma unroll
        for (int b = 0; b < 4; ++b)
#pragma unroll
            for (int d = 0; d < 4; ++d) c[a][b][d] = 0.f;

    for (int k0 = 0; k0 < HID; k0 += 16) {
#pragma unroll
        for (int l = 0; l < 2; ++l) {
            int idx = tid + l*256;
            int r = idx >> 2, c4 = (idx & 3) * 4;
            float4 va = *reinterpret_cast<const float4*>(&A[(size_t)(m0 + r)*HID + k0 + c4]);
            As[r][c4+0] = f2tf32(va.x); As[r][c4+1] = f2tf32(va.y);
            As[r][c4+2] = f2tf32(va.z); As[r][c4+3] = f2tf32(va.w);
            float4 vb = *reinterpret_cast<const float4*>(&Wm[(size_t)(n0 + r)*HID + k0 + c4]);
            Bs[r][c4+0] = f2tf32(vb.x); Bs[r][c4+1] = f2tf32(vb.y);
            Bs[r][c4+2] = f2tf32(vb.z); Bs[r][c4+3] = f2tf32(vb.w);
        }
        __syncthreads();
#pragma unroll
        for (int mi = 0; mi < 2; ++mi) {
            const int kk = mi*8 + (lane & 3);
            uint32_t af[4][4], bf[4][2];
#pragma unroll
            for (int mt = 0; mt < 4; ++mt) {
                int r = wm + mt*16 + (lane >> 2);
                af[mt][0] = As[r][kk];     af[mt][1] = As[r+8][kk];
                af[mt][2] = As[r][kk+4];   af[mt][3] = As[r+8][kk+4];
            }
#pragma unroll
            for (int nt = 0; nt < 4; ++nt) {
                int n = wn + nt*8 + (lane >> 2);
                bf[nt][0] = Bs[n][kk];     bf[nt][1] = Bs[n][kk+4];
            }
#pragma unroll
            for (int mt = 0; mt < 4; ++mt)
#pragma unroll
                for (int nt = 0; nt < 4; ++nt)
                    mma_tf32(c[mt][nt], af[mt][0], af[mt][1], af[mt][2], af[mt][3],
                             bf[nt][0], bf[nt][1]);
        }
        __syncthreads();
    }
#pragma unroll
    for (int mt = 0; mt < 4; ++mt) {
#pragma unroll
        for (int nt = 0; nt < 4; ++nt) {
            int ncol = n0 + wn + nt*8 + 2*(lane & 3);
            int h = ncol >> 6, d = ncol & 63;
            float b0 = bm[ncol], b1 = bm[ncol+1];
            int mA = m0 + wm + mt*16 + (lane >> 2);
            {
                int bi = mA >> 11, s = mA & 2047;
                float2 v = {c[mt][nt][0] + b0, c[mt][nt][1] + b1};
                *reinterpret_cast<float2*>(&Cdst[(((size_t)bi*NH + h)*SEQ + s)*HD + d]) = v;
            }
            {
                int mB = mA + 8;
                int bi = mB >> 11, s = mB & 2047;
                float2 v = {c[mt][nt][2] + b0, c[mt][nt][3] + b1};
                *reinterpret_cast<float2*>(&Cdst[(((size_t)bi*NH + h)*SEQ + s)*HD + d]) = v;
            }
        }
    }
}

// ---------------- 4) scores: attn_raw = scale * Q K^T per (b,h) --------------
// grid (16, 16, 32), 256 threads
__global__ void scores_mma_kernel(float* __restrict__ attn)
{
    __shared__ uint32_t As[128][20];
    __shared__ uint32_t Bs[128][20];
    const int z = blockIdx.z;
    const float* __restrict__ Az = g_QKV[0] + (size_t)z*SEQ*HD;
    const float* __restrict__ Bz = g_QKV[1] + (size_t)z*SEQ*HD;
    float* __restrict__ Cz = attn + (size_t)z*SEQ*SEQ;

    const int m0 = blockIdx.y * 128, n0 = blockIdx.x * 128;
    const int tid = threadIdx.x, lane = tid & 31, warp = tid >> 5;
    const int wm = (warp & 1) * 64, wn = (warp >> 1) * 32;

    float c[4][4][4];
#pragma unroll
    for (int a = 0; a < 4; ++a)
#pragma unroll
        for (int b = 0; b < 4; ++b)
#pragma unroll
            for (int d = 0; d < 4; ++d) c[a][b][d] = 0.f;

#pragma unroll
    for (int k0 = 0; k0 < HD; k0 += 16) {
#pragma unroll
        for (int l = 0; l < 2; ++l) {
            int idx = tid + l*256;
            int r = idx >> 2, c4 = (idx & 3) * 4;
            float4 va = *reinterpret_cast<const float4*>(&Az[(size_t)(m0 + r)*HD + k0 + c4]);
            As[r][c4+0] = f2tf32(va.x); As[r][c4+1] = f2tf32(va.y);
            As[r][c4+2] = f2tf32(va.z); As[r][c4+3] = f2tf32(va.w);
            float4 vb = *reinterpret_cast<const float4*>(&Bz[(size_t)(n0 + r)*HD + k0 + c4]);
            Bs[r][c4+0] = f2tf32(vb.x); Bs[r][c4+1] = f2tf32(vb.y);
            Bs[r][c4+2] = f2tf32(vb.z); Bs[r][c4+3] = f2tf32(vb.w);
        }
        __syncthreads();
#pragma unroll
        for (int mi = 0; mi < 2; ++mi) {
            const int kk = mi*8 + (lane & 3);
            uint32_t af[4][4], bf[4][2];
#pragma unroll
            for (int mt = 0; mt < 4; ++mt) {
                int r = wm + mt*16 + (lane >> 2);
                af[mt][0] = As[r][kk];     af[mt][1] = As[r+8][kk];
                af[mt][2] = As[r][kk+4];   af[mt][3] = As[r+8][kk+4];
            }
#pragma unroll
            for (int nt = 0; nt < 4; ++nt) {
                int n = wn + nt*8 + (lane >> 2);
                bf[nt][0] = Bs[n][kk];     bf[nt][1] = Bs[n][kk+4];
            }
#pragma unroll
            for (int mt = 0; mt < 4; ++mt)
#pragma unroll
                for (int nt = 0; nt < 4; ++nt)
                    mma_tf32(c[mt][nt], af[mt][0], af[mt][1], af[mt][2], af[mt][3],
                             bf[nt][0], bf[nt][1]);
        }
        __syncthreads();
    }
#pragma unroll
    for (int mt = 0; mt < 4; ++mt) {
#pragma unroll
        for (int nt = 0; nt < 4; ++nt) {
            int ncol = n0 + wn + nt*8 + 2*(lane & 3);
            int mA = m0 + wm + mt*16 + (lane >> 2);
            float2 v0 = {c[mt][nt][0]*SCALE_ATT, c[mt][nt][1]*SCALE_ATT};
            *reinterpret_cast<float2*>(&Cz[(size_t)mA*SEQ + ncol]) = v0;
            float2 v1 = {c[mt][nt][2]*SCALE_ATT, c[mt][nt][3]*SCALE_ATT};
            *reinterpret_cast<float2*>(&Cz[(size_t)(mA+8)*SEQ + ncol]) = v1;
        }
    }
}

// ---------------- 5) softmax over each row (in place) ----------------
__global__ void softmax_kernel(float* __restrict__ attn)
{
    __shared__ float row[SEQ];
    __shared__ float red[256];
    const size_t base = (size_t)blockIdx.x * SEQ;
    const int t = threadIdx.x;

    float m = -3.0e38f;
#pragma unroll
    for (int i = 0; i < 8; ++i) {
        float v = attn[base + t + i*256];
        row[t + i*256] = v;
        m = fmaxf(m, v);
    }
    red[t] = m; __syncthreads();
    for (int o = 128; o > 0; o >>= 1) {
        if (t < o) red[t] = fmaxf(red[t], red[t + o]);
        __syncthreads();
    }
    const float mx = red[0];
    __syncthreads();

    float ssum = 0.f;
#pragma unroll
    for (int i = 0; i < 8; ++i) {
        float e = __expf(row[t + i*256] - mx);
        row[t + i*256] = e;
        ssum += e;
    }
    red[t] = ssum; __syncthreads();
    for (int o = 128; o > 0; o >>= 1) {
        if (t < o) red[t] += red[t + o];
        __syncthreads();
    }
    const float inv = 1.0f / red[0];
#pragma unroll
    for (int i = 0; i < 8; ++i)
        attn[base + t + i*256] = row[t + i*256] * inv;
}

// ---------------- 5b) transpose V: [bh][s][d] -> [bh][d][s] ----------------
// grid (64, 2, 32), block (32, 8)
__global__ void transpose_V_kernel()
{
    __shared__ float t[32][33];
    const int z = blockIdx.z;
    const int s0 = blockIdx.x * 32, d0 = blockIdx.y * 32;
    const float* __restrict__ V = g_QKV[2] + (size_t)z*SEQ*HD;
    float* __restrict__ Vt = g_Vt + (size_t)z*HD*SEQ;
    const int tx = threadIdx.x, ty = threadIdx.y;
#pragma unroll
    for (int j = 0; j < 4; ++j)
        t[ty + 8*j][tx] = V[(size_t)(s0 + ty + 8*j)*HD + d0 + tx];
    __syncthreads();
#pragma unroll
    for (int j = 0; j < 4; ++j)
        Vt[(size_t)(d0 + ty + 8*j)*SEQ + s0 + tx] = t[tx][ty + 8*j];
}

// ---------------- 6) context = attn @ V, written to [B,S,HID] ----------------
// CTA tile 128x64, warps 4(M)x2(N), warp tile 32x32. grid (1, 16, 32)
__global__ void ctx_mma_kernel(const float* __restrict__ attn)
{
    __shared__ uint32_t As[128][20];
    __shared__ uint32_t Bs[64][20];
    const int z = blockIdx.z;
    const float* __restrict__ Az = attn + (size_t)z*SEQ*SEQ;
    const float* __restrict__ Bz = g_Vt + (size_t)z*HD*SEQ;

    const int m0 = blockIdx.y * 128;
    const int tid = threadIdx.x, lane = tid & 31, warp = tid >> 5;
    const int wm = (warp >> 1) * 32, wn = (warp & 1) * 32;

    float c[2][4][4];
#pragma unroll
    for (int a = 0; a < 2; ++a)
#pragma unroll
        for (int b = 0; b < 4; ++b)
#pragma unroll
            for (int d = 0; d < 4; ++d) c[a][b][d] = 0.f;

    for (int k0 = 0; k0 < SEQ; k0 += 16) {
#pragma unroll
        for (int l = 0; l < 2; ++l) {
            int idx = tid + l*256;
            int r = idx >> 2, c4 = (idx & 3) * 4;
            float4 va = *reinterpret_cast<const float4*>(&Az[(size_t)(m0 + r)*SEQ + k0 + c4]);
            As[r][c4+0] = f2tf32(va.x); As[r][c4+1] = f2tf32(va.y);
            As[r][c4+2] = f2tf32(va.z); As[r][c4+3] = f2tf32(va.w);
        }
        {
            int r = tid >> 2, c4 = (tid & 3) * 4;   // 64 rows x 4 float4
            float4 vb = *reinterpret_cast<const float4*>(&Bz[(size_t)r*SEQ + k0 + c4]);
            Bs[r][c4+0] = f2tf32(vb.x); Bs[r][c4+1] = f2tf32(vb.y);
            Bs[r][c4+2] = f2tf32(vb.z); Bs[r][c4+3] = f2tf32(vb.w);
        }
        __syncthreads();
#pragma unroll
        for (int mi = 0; mi < 2; ++mi) {
            const int kk = mi*8 + (lane & 3);
            uint32_t af[2][4], bf[4][2];
#pragma unroll
            for (int mt = 0; mt < 2; ++mt) {
                int r = wm + mt*16 + (lane >> 2);
                af[mt][0] = As[r][kk];     af[mt][1] = As[r+8][kk];
                af[mt][2] = As[r][kk+4];   af[mt][3] = As[r+8][kk+4];
            }
#pragma unroll
            for (int nt = 0; nt < 4; ++nt) {
                int n = wn + nt*8 + (lane >> 2);
                bf[nt][0] = Bs[n][kk];     bf[nt][1] = Bs[n][kk+4];
            }
#pragma unroll
            for (int mt = 0; mt < 2; ++mt)
#pragma unroll
                for (int nt = 0; nt < 4; ++nt)
                    mma_tf32(c[mt][nt], af[mt][0], af[mt][1], af[mt][2], af[mt][3],
                             bf[nt][0], bf[nt][1]);
        }
        __syncthreads();
    }
    const int bi = z >> 4, h = z & 15;
#pragma unroll
    for (int mt = 0; mt < 2; ++mt) {
#pragma unroll
        for (int nt = 0; nt < 4; ++nt) {
            int d = wn + nt*8 + 2*(lane & 3);
            int qA = m0 + wm + mt*16 + (lane >> 2);
            float2 v0 = {c[mt][nt][0], c[mt][nt][1]};
            *reinterpret_cast<float2*>(&g_ctx[((size_t)bi*SEQ + qA)*HID + (h<<6) + d]) = v0;
            float2 v1 = {c[mt][nt][2], c[mt][nt][3]};
            *reinterpret_cast<float2*>(&g_ctx[((size_t)bi*SEQ + qA + 8)*HID + (h<<6) + d]) = v1;
        }
    }
}

// ---------------- 7) output = ctx @ Wo^T + bo ----------------
// grid (8, 32), 256 threads
__global__ void out_mma_kernel(const float* __restrict__ Wo,
                               const float* __restrict__ bo,
                               float* __restrict__ out)
{
    __shared__ uint32_t As[128][20];
    __shared__ uint32_t Bs[128][20];
    const int m0 = blockIdx.y * 128, n0 = blockIdx.x * 128;
    const int tid = threadIdx.x, lane = tid & 31, warp = tid >> 5;
    const int wm = (warp & 1) * 64, wn = (warp >> 1) * 32;

    float c[4][4][4];
#pragma unroll
    for (int a = 0; a < 4; ++a)
#pragma unroll
        for (int b = 0; b < 4; ++b)
#pragma unroll
            for (int d = 0; d < 4; ++d) c[a][b][d] = 0.f;

    for (int k0 = 0; k0 < HID; k0 += 16) {
#pragma unroll
        for (int l = 0; l < 2; ++l) {
            int idx = tid + l*256;
            int r = idx >> 2, c4 = (idx & 3) * 4;
            float4 va = *reinterpret_cast<const float4*>(&g_ctx[(size_t)(m0 + r)*HID + k0 + c4]);
            As[r][c4+0] = f2tf32(va.x); As[r][c4+1] = f2tf32(va.y);
            As[r][c4+2] = f2tf32(va.z); As[r][c4+3] = f2tf32(va.w);
            float4 vb = *reinterpret_cast<const float4*>(&Wo[(size_t)(n0 + r)*HID + k0 + c4]);
            Bs[r][c4+0] = f2tf32(vb.x); Bs[r][c4+1] = f2tf32(vb.y);
            Bs[r][c4+2] = f2tf32(vb.z); Bs[r][c4+3] = f2tf32(vb.w);
        }
        __syncthreads();
#pragma unroll
        for (int mi = 0; mi < 2; ++mi) {
            const int kk = mi*8 + (lane & 3);
            uint32_t af[4][4], bf[4][2];
#pragma unroll
            for (int mt = 0; mt < 4; ++mt) {
                int r = wm + mt*16 + (lane >> 2);
                af[mt][0] = As[r][kk];     af[mt][1] = As[r+8][kk];
                af[mt][2] = As[r][kk+4];   af[mt][3] = As[r+8][kk+4];
            }
#pragma unroll
            for (int nt = 0; nt < 4; ++nt) {
                int n = wn + nt*8 + (lane >> 2);
                bf[nt][0] = Bs[n][kk];     bf[nt][1] = Bs[n][kk+4];
            }
#pragma unroll
            for (int mt = 0; mt < 4; ++mt)
#pragma unroll
                for (int nt = 0; nt < 4; ++nt)
                    mma_tf32(c[mt][nt], af[mt][0], af[mt][1], af[mt][2], af[mt][3],
                             bf[nt][0], bf[nt][1]);
        }
        __syncthreads();
    }
#pragma unroll
    for (int mt = 0; mt < 4; ++mt) {
#pragma unroll
        for (int nt = 0; nt < 4; ++nt) {
            int ncol = n0 + wn + nt*8 + 2*(lane & 3);
            float b0 = bo[ncol], b1 = bo[ncol+1];
            int mA = m0 + wm + mt*16 + (lane >> 2);
            float2 v0 = {c[mt][nt][0] + b0, c[mt][nt][1] + b1};
            *reinterpret_cast<float2*>(&out[(size_t)mA*HID + ncol]) = v0;
            float2 v1 = {c[mt][nt][2] + b0, c[mt][nt][3] + b1};
            *reinterpret_cast<float2*>(&out[(size_t)(mA+8)*HID + ncol]) = v1;
        }
    }
}

// ---------------- launch ----------------
extern "C" void kernel_launch(void* const* d_in, const int* in_sizes, int n_in,
                              void* d_out, int out_size)
{
    const float* query = (const float*)d_in[0];
    const float* key   = (const float*)d_in[1];
    const float* value = (const float*)d_in[2];
    const float* Wq = (const float*)d_in[3];  const float* bq = (const float*)d_in[4];
    const float* Wk = (const float*)d_in[5];  const float* bk = (const float*)d_in[6];
    const float* Wv = (const float*)d_in[7];  const float* bv = (const float*)d_in[8];
    const float* Wo = (const float*)d_in[9];  const float* bo = (const float*)d_in[10];
    const float* ent_w = (const float*)d_in[11];
    const float* ent_s = (const float*)d_in[12];
    const float* sup_w = (const float*)d_in[13];
    const float* sup_c = (const float*)d_in[14];

    float* out  = (float*)d_out;                 // [B,S,HID]
    float* attn = (float*)d_out + OUT_ELEMS;     // [B,NH,S,S]
    (void)in_sizes; (void)n_in; (void)out_size;

    // 1) composite 64x64 transforms
    build_T_kernel<<<1, 128>>>(ent_w, ent_s, sup_w, sup_c);

    // 2) fold transforms into projection weights
    dim3 tgrid(16, 16);
    transform_W_kernel<<<tgrid, 256>>>(Wq, bq, 0);
    transform_W_kernel<<<tgrid, 256>>>(Wk, bk, 1);
    transform_W_kernel<<<tgrid, 256>>>(Wv, bv, 2);

    // 3) projections (tf32 mma)
    dim3 pgrid(HID/128, MROWS/128);
    proj_mma_kernel<<<pgrid, 256>>>(query, 0);
    proj_mma_kernel<<<pgrid, 256>>>(key,   1);
    proj_mma_kernel<<<pgrid, 256>>>(value, 2);

    // 4) raw scores
    dim3 sgrid(SEQ/128, SEQ/128, BH);
    scores_mma_kernel<<<sgrid, 256>>>(attn);

    // 5) softmax in place + V transpose
    softmax_kernel<<<BH*SEQ, 256>>>(attn);
    transpose_V_kernel<<<dim3(SEQ/32, HD/32, BH), dim3(32, 8)>>>();

    // 6) context (tf32 mma)
    dim3 cgrid(1, SEQ/128, BH);
    ctx_mma_kernel<<<cgrid, 256>>>(attn);

    // 7) output projection (tf32 mma)
    dim3 ogrid(HID/128, MROWS/128);
    out_mma_kernel<<<ogrid, 256>>>(Wo, bo, out);
}

// round 7
// speedup vs baseline: 3.8994x; 1.1421x over previous
#include <cuda_runtime.h>
#include <cstdint>
#include <cstddef>

// Problem constants
#define BATCH 2
#define SEQ   2048
#define HID   1024
#define NH    16
#define HD    64
#define BH    (BATCH*NH)            // 32
#define MROWS (BATCH*SEQ)           // 4096
#define SCALE_ATT 0.125f            // 1/sqrt(64)
#define OUT_ELEMS ((size_t)BATCH*SEQ*HID)          // 4,194,304

// ---------------- device scratch (no allocs allowed) ----------------
__device__ float g_T[2][64*64];                 // 0: T for Q/K, 1: T for V
__device__ float g_Wt[3][HID*HID];              // transformed Wq,Wk,Wv
__device__ float g_bt[3][HID];
__device__ float g_QKV[3][(size_t)BH*SEQ*HD];   // Qq,Kq,Vq  [B,NH,S,D]
__device__ float g_Vt[(size_t)BH*HD*SEQ];       // V transposed [bh][d][s]
__device__ float g_ctx[(size_t)MROWS*HID];      // context   [B,S,HID]

// ---------------- tf32 mma helpers ----------------
__device__ __forceinline__ uint32_t f2tf32(float f) {
    uint32_t r;
    asm("cvt.rna.tf32.f32 %0, %1;" : "=r"(r) : "f"(f));
    return r;
}
__device__ __forceinline__ void mma_tf32(float c[4],
                                         uint32_t a0, uint32_t a1, uint32_t a2, uint32_t a3,
                                         uint32_t b0, uint32_t b1) {
    asm volatile(
        "mma.sync.aligned.m16n8k8.row.col.f32.tf32.tf32.f32 "
        "{%0,%1,%2,%3}, {%4,%5,%6,%7}, {%8,%9}, {%0,%1,%2,%3};"
        : "+f"(c[0]), "+f"(c[1]), "+f"(c[2]), "+f"(c[3])
        : "r"(a0), "r"(a1), "r"(a2), "r"(a3), "r"(b0), "r"(b1));
}

// ---------------- 1) build the 64x64 composite transforms ----------------
__global__ void build_T_kernel(const float* __restrict__ ent_w,  // [4,16,16]
                               const float* __restrict__ ent_s,  // [4]
                               const float* __restrict__ sup_w,  // [8,64]
                               const float* __restrict__ sup_c)  // [8]
{
    int t = threadIdx.x;
    if (t >= 128) return;
    int v = t >> 6;      // 0: QK path, 1: V path
    int i = t & 63;

    float x[64];
#pragma unroll
    for (int j = 0; j < 64; ++j) x[j] = (j == i) ? 1.0f : 0.0f;

    float w[64];
    for (int p = 0; p < 4; ++p)
        for (int j = 0; j < 16; ++j) {
            float acc = 0.f;
            for (int ii = 0; ii < 16; ++ii)
                acc += x[p*16 + ii] * ent_w[p*256 + ii*16 + j];
            w[p*16 + j] = acc;
        }
    for (int g = 0; g < 16; ++g) {
        float sc = ent_s[g >> 2];
        x[4*g+0] = w[4*g+0]*sc;
        x[4*g+1] = w[4*g+1]*sc;
        x[4*g+2] = w[4*g+3]*sc;
        x[4*g+3] = w[4*g+2]*sc;
    }
    const float R = 0.70710678118654752440f;
    for (int pr = 0; pr < 32; ++pr) {
        float a = x[2*pr], b = x[2*pr+1];
        x[2*pr]   = (a + b) * R;
        x[2*pr+1] = (a - b) * R;
    }
    for (int d = 0; d < 64; ++d) {
        float s = 0.f;
        for (int n = 0; n < 8; ++n) s += sup_c[n] * sup_w[n*64 + d];
        x[d] *= s;
    }
    if (v == 0) {
        for (int pr = 0; pr < 32; ++pr) {
            float a = x[2*pr], b = x[2*pr+1];
            x[2*pr]   = (a + b) * R;
            x[2*pr+1] = (a - b) * R;
        }
    } else {
        for (int g = 0; g < 16; ++g) {
            float a = x[4*g+2];
            x[4*g+2] = x[4*g+3];
            x[4*g+3] = a;
        }
    }
#pragma unroll
    for (int j = 0; j < 64; ++j) g_T[v][i*64 + j] = x[j];
}

// ---------------- 2) fold T into projection weights (smem-tiled) ----------
__global__ void transform_W_kernel(const float* __restrict__ W,
                                   const float* __restrict__ bvec,
                                   int mat)
{
    __shared__ float Ts[64][65];
    __shared__ float Ws[64][65];
    const float* __restrict__ T = g_T[(mat == 2) ? 1 : 0];
    const int head = blockIdx.y;
    const int k0 = blockIdx.x * 64;
    const int tid = threadIdx.x;

#pragma unroll
    for (int l = 0; l < 16; ++l) {
        int idx = tid + l*256;
        int i = idx >> 6, c = idx & 63;
        Ts[i][c] = T[idx];
        Ws[i][c] = W[(size_t)(head*64 + i)*HID + k0 + c];
    }
    __syncthreads();

    const int k = tid & 63, g = tid >> 6;   // g in 0..3, 16 ml values each
    float acc[16] = {};
    for (int i = 0; i < 64; ++i) {
        float wv = Ws[i][k];
#pragma unroll
        for (int j = 0; j < 16; ++j)
            acc[j] += Ts[i][g*16 + j] * wv;
    }
#pragma unroll
    for (int j = 0; j < 16; ++j)
        g_Wt[mat][(size_t)(head*64 + g*16 + j)*HID + k0 + k] = acc[j];

    if (blockIdx.x == 0 && tid < 64) {
        float ab = 0.f;
        for (int i = 0; i < 64; ++i)
            ab += Ts[i][tid] * bvec[head*64 + i];
        g_bt[mat][head*64 + tid] = ab;
    }
}

// ---------------- 3) projection: C = A * W'^T + b', scatter [B,NH,S,D] ------
__global__ void proj_mma_kernel(const float* __restrict__ A, int mat)
{
    __shared__ uint32_t As[128][20];
    __shared__ uint32_t Bs[128][20];
    const float* __restrict__ Wm = g_Wt[mat];
    const float* __restrict__ bm = g_bt[mat];
    float* __restrict__ Cdst = g_QKV[mat];

    const int m0 = blockIdx.y * 128, n0 = blockIdx.x * 128;
    const int tid = threadIdx.x, lane = tid & 31, warp = tid >> 5;
    const int wm = (warp & 1) * 64, wn = (warp >> 1) * 32;

    float c[4][4][4];
#pragma unroll
    for (int a = 0; a < 4; ++a)
#pragma unroll
        for (int b = 0; b < 4; ++b)
#pragma unroll
            for (int d = 0; d < 4; ++d) c[a][b][d] = 0.f;

    for (int k0 = 0; k0 < HID; k0 += 16) {
#pragma unroll
        for (int l = 0; l < 2; ++l) {
            int idx = tid + l*256;
            int r = idx >> 2, c4 = (idx & 3) * 4;
            float4 va = *reinterpret_cast<const float4*>(&A[(size_t)(m0 + r)*HID + k0 + c4]);
            As[r][c4+0] = f2tf32(va.x); As[r][c4+1] = f2tf32(va.y);
            As[r][c4+2] = f2tf32(va.z); As[r][c4+3] = f2tf32(va.w);
            float4 vb = *reinterpret_cast<const float4*>(&Wm[(size_t)(n0 + r)*HID + k0 + c4]);
            Bs[r][c4+0] = f2tf32(vb.x); Bs[r][c4+1] = f2tf32(vb.y);
            Bs[r][c4+2] = f2tf32(vb.z); Bs[r][c4+3] = f2tf32(vb.w);
        }
        __syncthreads();
#pragma unroll
        for (int mi = 0; mi < 2; ++mi) {
            const int kk = mi*8 + (lane & 3);
            uint32_t af[4][4], bf[4][2];
#pragma unroll
            for (int mt = 0; mt < 4; ++mt) {
                int r = wm + mt*16 + (lane >> 2);
                af[mt][0] = As[r][kk];     af[mt][1] = As[r+8][kk];
                af[mt][2] = As[r][kk+4];   af[mt][3] = As[r+8][kk+4];
            }
#pragma unroll
            for (int nt = 0; nt < 4; ++nt) {
                int n = wn + nt*8 + (lane >> 2);
                bf[nt][0] = Bs[n][kk];     bf[nt][1] = Bs[n][kk+4];
            }
#pragma unroll
            for (int mt = 0; mt < 4; ++mt)
#pragma unroll
                for (int nt = 0; nt < 4; ++nt)
                    mma_tf32(c[mt][nt], af[mt][0], af[mt][1], af[mt][2], af[mt][3],
                             bf[nt][0], bf[nt][1]);
        }
        __syncthreads();
    }
#pragma unroll
    for (int mt = 0; mt < 4; ++mt) {
#pragma unroll
        for (int nt = 0; nt < 4; ++nt) {
            int ncol = n0 + wn + nt*8 + 2*(lane & 3);
            int h = ncol >> 6, d = ncol & 63;
            float b0 = bm[ncol], b1 = bm[ncol+1];
            int mA = m0 + wm + mt*16 + (lane >> 2);
            {
                int bi = mA >> 11, s = mA & 2047;
                float2 v = {c[mt][nt][0] + b0, c[mt][nt][1] + b1};
                *reinterpret_cast<float2*>(&Cdst[(((size_t)bi*NH + h)*SEQ + s)*HD + d]) = v;
            }
            {
                int mB = mA + 8;
                int bi = mB >> 11, s = mB & 2047;
                float2 v = {c[mt][nt][2] + b0, c[mt][nt][3] + b1};
                *reinterpret_cast<float2*>(&Cdst[(((size_t)bi*NH + h)*SEQ + s)*HD + d]) = v;
            }
        }
    }
}

// ---------------- 4) transpose V: [bh][s][d] -> [bh][d][s] ----------------
__global__ void transpose_V_kernel()
{
    __shared__ float t[32][33];
    const int z = blockIdx.z;
    const int s0 = blockIdx.x * 32, d0 = blockIdx.y * 32;
    const float* __restrict__ V = g_QKV[2] + (size_t)z*SEQ*HD;
    float* __restrict__ Vt = g_Vt + (size_t)z*HD*SEQ;
    const int tx = threadIdx.x, ty = threadIdx.y;
#pragma unroll
    for (int j = 0; j < 4; ++j)
        t[ty + 8*j][tx] = V[(size_t)(s0 + ty + 8*j)*HD + d0 + tx];
    __syncthreads();
#pragma unroll
    for (int j = 0; j < 4; ++j)
        Vt[(size_t)(d0 + ty + 8*j)*SEQ + s0 + tx] = t[tx][ty + 8*j];
}

// ---------------- 5) flash attention: stats pass + prob/PV pass ------------
// grid (SEQ/128=16, BH=32), 256 threads, dynamic smem ~174.6 KB
// Writes normalized probabilities to attn (only touch of attn) and context
// to g_ctx.
// smem layout (uint32 units):
//   Qs [128][68]  @ 0       (tf32, pre-scaled by 1/8)
//   Ks [128][68]  @ 8704
//   Vs [64][132]  @ 17408   (tf32, Vt tile: [d][s])
//   Ps [128][132] @ 25856   (tf32 probabilities)
//   stats (floats) @ 42752: sM[128], sSum[128], sTmax[128], spart[128][4]
#define FL_Q  0
#define FL_K  8704
#define FL_V  17408
#define FL_P  25856
#define FL_ST 42752
#define FL_SMEM_BYTES ((42752 + 128*3 + 512) * 4)   // 174592

__global__ void flash_kernel(float* __restrict__ attn)
{
    extern __shared__ uint32_t sm[];
    uint32_t (*Qs)[68]  = reinterpret_cast<uint32_t(*)[68]>(sm + FL_Q);
    uint32_t (*Ks)[68]  = reinterpret_cast<uint32_t(*)[68]>(sm + FL_K);
    uint32_t (*Vs)[132] = reinterpret_cast<uint32_t(*)[132]>(sm + FL_V);
    uint32_t (*Ps)[132] = reinterpret_cast<uint32_t(*)[132]>(sm + FL_P);
    float* sM    = reinterpret_cast<float*>(sm + FL_ST);
    float* sSum  = sM + 128;
    float* sTmax = sSum + 128;
    float (*spart)[4] = reinterpret_cast<float(*)[4]>(sTmax + 128);

    const int z  = blockIdx.y;
    const int m0 = blockIdx.x * 128;
    const float* __restrict__ Qg  = g_QKV[0] + (size_t)z*SEQ*HD;
    const float* __restrict__ Kg  = g_QKV[1] + (size_t)z*SEQ*HD;
    const float* __restrict__ Vtg = g_Vt     + (size_t)z*HD*SEQ;
    float* __restrict__ Cz = attn + (size_t)z*SEQ*SEQ;

    const int tid = threadIdx.x, lane = tid & 31, warp = tid >> 5;
    const int wm  = (warp & 1) * 64;      // S rows (and O rows)
    const int wn  = (warp >> 1) * 32;     // S cols slice
    const int wno = (warp >> 1) * 16;     // O cols slice
    const int slice = warp >> 1;

    // ---- stage Q tile once (scaled by SCALE_ATT) ----
#pragma unroll
    for (int l = 0; l < 8; ++l) {
        int idx = tid + l*256;
        int r = idx >> 4, c4 = (idx & 15) * 4;
        float4 v = *reinterpret_cast<const float4*>(&Qg[(size_t)(m0 + r)*HD + c4]);
        Qs[r][c4+0] = f2tf32(v.x * SCALE_ATT);
        Qs[r][c4+1] = f2tf32(v.y * SCALE_ATT);
        Qs[r][c4+2] = f2tf32(v.z * SCALE_ATT);
        Qs[r][c4+3] = f2tf32(v.w * SCALE_ATT);
    }
    if (tid < 128) { sM[tid] = -3.0e38f; sSum[tid] = 0.f; }

    int rowA[4];
#pragma unroll
    for (int mt = 0; mt < 4; ++mt) rowA[mt] = wm + mt*16 + (lane >> 2);

    // ================= pass 1: online row max + sumexp =================
    for (int j = 0; j < 16; ++j) {
        // stage K tile
#pragma unroll
        for (int l = 0; l < 8; ++l) {
            int idx = tid + l*256;
            int r = idx >> 4, c4 = (idx & 15) * 4;
            float4 v = *reinterpret_cast<const float4*>(&Kg[(size_t)(j*128 + r)*HD + c4]);
            Ks[r][c4+0] = f2tf32(v.x); Ks[r][c4+1] = f2tf32(v.y);
            Ks[r][c4+2] = f2tf32(v.z); Ks[r][c4+3] = f2tf32(v.w);
        }
        __syncthreads();

        float c[4][4][4];
#pragma unroll
        for (int a = 0; a < 4; ++a)
#pragma unroll
            for (int b = 0; b < 4; ++b)
#pragma unroll
                for (int d = 0; d < 4; ++d) c[a][b][d] = 0.f;

#pragma unroll
        for (int ks = 0; ks < 8; ++ks) {
            const int kk = ks*8 + (lane & 3);
            uint32_t af[4][4], bf[4][2];
#pragma unroll
            for (int mt = 0; mt < 4; ++mt) {
                int r = rowA[mt];
                af[mt][0] = Qs[r][kk];     af[mt][1] = Qs[r+8][kk];
                af[mt][2] = Qs[r][kk+4];   af[mt][3] = Qs[r+8][kk+4];
            }
#pragma unroll
            for (int nt = 0; nt < 4; ++nt) {
                int n = wn + nt*8 + (lane >> 2);
                bf[nt][0] = Ks[n][kk];     bf[nt][1] = Ks[n][kk+4];
            }
#pragma unroll
            for (int mt = 0; mt < 4; ++mt)
#pragma unroll
                for (int nt = 0; nt < 4; ++nt)
                    mma_tf32(c[mt][nt], af[mt][0], af[mt][1], af[mt][2], af[mt][3],
                             bf[nt][0], bf[nt][1]);
        }

        // row max over the warp's 32-col slice
        float rmax[4][2];
#pragma unroll
        for (int mt = 0; mt < 4; ++mt) {
            float m0v = -3.0e38f, m1v = -3.0e38f;
#pragma unroll
            for (int nt = 0; nt < 4; ++nt) {
                m0v = fmaxf(m0v, fmaxf(c[mt][nt][0], c[mt][nt][1]));
                m1v = fmaxf(m1v, fmaxf(c[mt][nt][2], c[mt][nt][3]));
            }
            rmax[mt][0] = m0v; rmax[mt][1] = m1v;
        }
#pragma unroll
        for (int mt = 0; mt < 4; ++mt) {
#pragma unroll
            for (int h2 = 0; h2 < 2; ++h2) {
                float v = rmax[mt][h2];
                v = fmaxf(v, __shfl_xor_sync(0xffffffffu, v, 1));
                v = fmaxf(v, __shfl_xor_sync(0xffffffffu, v, 2));
                rmax[mt][h2] = v;
            }
        }
        if ((lane & 3) == 0) {
#pragma unroll
            for (int mt = 0; mt < 4; ++mt) {
                spart[rowA[mt]][slice]     = rmax[mt][0];
                spart[rowA[mt] + 8][slice] = rmax[mt][1];
            }
        }
        __syncthreads();
        if (tid < 128) {
            float tm = fmaxf(fmaxf(spart[tid][0], spart[tid][1]),
                             fmaxf(spart[tid][2], spart[tid][3]));
            sTmax[tid] = tm;
        }
        __syncthreads();

        // sumexp with tile max
        float esum[4][2];
#pragma unroll
        for (int mt = 0; mt < 4; ++mt) {
            float tA = sTmax[rowA[mt]], tB = sTmax[rowA[mt] + 8];
            float s0 = 0.f, s1 = 0.f;
#pragma unroll
            for (int nt = 0; nt < 4; ++nt) {
                s0 += __expf(c[mt][nt][0] - tA) + __expf(c[mt][nt][1] - tA);
                s1 += __expf(c[mt][nt][2] - tB) + __expf(c[mt][nt][3] - tB);
            }
            esum[mt][0] = s0; esum[mt][1] = s1;
        }
#pragma unroll
        for (int mt = 0; mt < 4; ++mt) {
#pragma unroll
            for (int h2 = 0; h2 < 2; ++h2) {
                float v = esum[mt][h2];
                v += __shfl_xor_sync(0xffffffffu, v, 1);
                v += __shfl_xor_sync(0xffffffffu, v, 2);
                esum[mt][h2] = v;
            }
        }
        __syncthreads();   // spart reuse
        if ((lane & 3) == 0) {
#pragma unroll
            for (int mt = 0; mt < 4; ++mt) {
                spart[rowA[mt]][slice]     = esum[mt][0];
                spart[rowA[mt] + 8][slice] = esum[mt][1];
            }
        }
        __syncthreads();
        if (tid < 128) {
            float ts = spart[tid][0] + spart[tid][1] + spart[tid][2] + spart[tid][3];
            float mo = sM[tid], tm = sTmax[tid];
            float mn = fmaxf(mo, tm);
            sSum[tid] = sSum[tid]*__expf(mo - mn) + ts*__expf(tm - mn);
            sM[tid] = mn;
        }
        __syncthreads();
    }

    if (tid < 128) sSum[tid] = 1.0f / sSum[tid];
    __syncthreads();

    // cache per-row stats in registers
    float Mr[4][2], Ir[4][2];
#pragma unroll
    for (int mt = 0; mt < 4; ++mt) {
        Mr[mt][0] = sM[rowA[mt]];      Mr[mt][1] = sM[rowA[mt] + 8];
        Ir[mt][0] = sSum[rowA[mt]];    Ir[mt][1] = sSum[rowA[mt] + 8];
    }

    float co[4][2][4];
#pragma unroll
    for (int a = 0; a < 4; ++a)
#pragma unroll
        for (int b = 0; b < 2; ++b)
#pragma unroll
            for (int d = 0; d < 4; ++d) co[a][b][d] = 0.f;

    // ================= pass 2: probs -> attn, P*V -> ctx =================
    for (int j = 0; j < 16; ++j) {
        // stage K tile + Vt tile
#pragma unroll
        for (int l = 0; l < 8; ++l) {
            int idx = tid + l*256;
            int r = idx >> 4, c4 = (idx & 15) * 4;
            float4 v = *reinterpret_cast<const float4*>(&Kg[(size_t)(j*128 + r)*HD + c4]);
            Ks[r][c4+0] = f2tf32(v.x); Ks[r][c4+1] = f2tf32(v.y);
            Ks[r][c4+2] = f2tf32(v.z); Ks[r][c4+3] = f2tf32(v.w);
        }
#pragma unroll
        for (int l = 0; l < 8; ++l) {
            int idx = tid + l*256;
            int d = idx >> 5, s4 = (idx & 31) * 4;
            float4 v = *reinterpret_cast<const float4*>(&Vtg[(size_t)d*SEQ + j*128 + s4]);
            Vs[d][s4+0] = f2tf32(v.x); Vs[d][s4+1] = f2tf32(v.y);
            Vs[d][s4+2] = f2tf32(v.z); Vs[d][s4+3] = f2tf32(v.w);
        }
        __syncthreads();

        // recompute S tile
        float c[4][4][4];
#pragma unroll
        for (int a = 0; a < 4; ++a)
#pragma unroll
            for (int b = 0; b < 4; ++b)
#pragma unroll
                for (int d = 0; d < 4; ++d) c[a][b][d] = 0.f;
#pragma unroll
        for (int ks = 0; ks < 8; ++ks) {
            const int kk = ks*8 + (lane & 3);
            uint32_t af[4][4], bf[4][2];
#pragma unroll
            for (int mt = 0; mt < 4; ++mt) {
                int r = rowA[mt];
                af[mt][0] = Qs[r][kk];     af[mt][1] = Qs[r+8][kk];
                af[mt][2] = Qs[r][kk+4];   af[mt][3] = Qs[r+8][kk+4];
            }
#pragma unroll
            for (int nt = 0; nt < 4; ++nt) {
                int n = wn + nt*8 + (lane >> 2);
                bf[nt][0] = Ks[n][kk];     bf[nt][1] = Ks[n][kk+4];
            }
#pragma unroll
            for (int mt = 0; mt < 4; ++mt)
#pragma unroll
                for (int nt = 0; nt < 4; ++nt)
                    mma_tf32(c[mt][nt], af[mt][0], af[mt][1], af[mt][2], af[mt][3],
                             bf[nt][0], bf[nt][1]);
        }

        // probabilities: write to attn + stage to Ps
#pragma unroll
        for (int mt = 0; mt < 4; ++mt) {
#pragma unroll
            for (int nt = 0; nt < 4; ++nt) {
                int cl = wn + nt*8 + 2*(lane & 3);
                int colg = j*128 + cl;
                float p0 = __expf(c[mt][nt][0] - Mr[mt][0]) * Ir[mt][0];
                float p1 = __expf(c[mt][nt][1] - Mr[mt][0]) * Ir[mt][0];
                float p2 = __expf(c[mt][nt][2] - Mr[mt][1]) * Ir[mt][1];
                float p3 = __expf(c[mt][nt][3] - Mr[mt][1]) * Ir[mt][1];
                int r = rowA[mt];
                float2 v0 = {p0, p1};
                *reinterpret_cast<float2*>(&Cz[(size_t)(m0 + r)*SEQ + colg]) = v0;
                float2 v1 = {p2, p3};
                *reinterpret_cast<float2*>(&Cz[(size_t)(m0 + r + 8)*SEQ + colg]) = v1;
                Ps[r][cl]     = f2tf32(p0);  Ps[r][cl+1]   = f2tf32(p1);
                Ps[r+8][cl]   = f2tf32(p2);  Ps[r+8][cl+1] = f2tf32(p3);
            }
        }
        __syncthreads();

        // O += P * V   (A = Ps 128x128, B = Vs [d][s] 64x128)
#pragma unroll
        for (int ks = 0; ks < 16; ++ks) {
            const int kk = ks*8 + (lane & 3);
            uint32_t af[4][4], bf[2][2];
#pragma unroll
            for (int mt = 0; mt < 4; ++mt) {
                int r = rowA[mt];
                af[mt][0] = Ps[r][kk];     af[mt][1] = Ps[r+8][kk];
                af[mt][2] = Ps[r][kk+4];   af[mt][3] = Ps[r+8][kk+4];
            }
#pragma unroll
            for (int nt = 0; nt < 2; ++nt) {
                int n = wno + nt*8 + (lane >> 2);
                bf[nt][0] = Vs[n][kk];     bf[nt][1] = Vs[n][kk+4];
            }
#pragma unroll
            for (int mt = 0; mt < 4; ++mt)
#pragma unroll
                for (int nt = 0; nt < 2; ++nt)
                    mma_tf32(co[mt][nt], af[mt][0], af[mt][1], af[mt][2], af[mt][3],
                             bf[nt][0], bf[nt][1]);
        }
        __syncthreads();
    }

    // epilogue: context to g_ctx [B,S,HID]
    const int bi = z >> 4, h = z & 15;
#pragma unroll
    for (int mt = 0; mt < 4; ++mt) {
#pragma unroll
        for (int nt = 0; nt < 2; ++nt) {
            int d = wno + nt*8 + 2*(lane & 3);
            int q = m0 + rowA[mt];
            float2 v0 = {co[mt][nt][0], co[mt][nt][1]};
            *reinterpret_cast<float2*>(&g_ctx[((size_t)bi*SEQ + q)*HID + (h<<6) + d]) = v0;
            float2 v1 = {co[mt][nt][2], co[mt][nt][3]};
            *reinterpret_cast<float2*>(&g_ctx[((size_t)bi*SEQ + q + 8)*HID + (h<<6) + d]) = v1;
        }
    }
}

// ---------------- 6) output = ctx @ Wo^T + bo ----------------
__global__ void out_mma_kernel(const float* __restrict__ Wo,
                               const float* __restrict__ bo,
                               float* __restrict__ out)
{
    __shared__ uint32_t As[128][20];
    __shared__ uint32_t Bs[128][20];
    const int m0 = blockIdx.y * 128, n0 = blockIdx.x * 128;
    const int tid = threadIdx.x, lane = tid & 31, warp = tid >> 5;
    const int wm = (warp & 1) * 64, wn = (warp >> 1) * 32;

    float c[4][4][4];
#pragma unroll
    for (int a = 0; a < 4; ++a)
#pragma unroll
        for (int b = 0; b < 4; ++b)
#pragma unroll
            for (int d = 0; d < 4; ++d) c[a][b][d] = 0.f;

    for (int k0 = 0; k0 < HID; k0 += 16) {
#pragma unroll
        for (int l = 0; l < 2; ++l) {
            int idx = tid + l*256;
            int r = idx >> 2, c4 = (idx & 3) * 4;
            float4 va = *reinterpret_cast<const float4*>(&g_ctx[(size_t)(m0 + r)*HID + k0 + c4]);
            As[r][c4+0] = f2tf32(va.x); As[r][c4+1] = f2tf32(va.y);
            As[r][c4+2] = f2tf32(va.z); As[r][c4+3] = f2tf32(va.w);
            float4 vb = *reinterpret_cast<const float4*>(&Wo[(size_t)(n0 + r)*HID + k0 + c4]);
            Bs[r][c4+0] = f2tf32(vb.x); Bs[r][c4+1] = f2tf32(vb.y);
            Bs[r][c4+2] = f2tf32(vb.z); Bs[r][c4+3] = f2tf32(vb.w);
        }
        __syncthreads();
#pragma unroll
        for (int mi = 0; mi < 2; ++mi) {
            const int kk = mi*8 + (lane & 3);
            uint32_t af[4][4], bf[4][2];
#pragma unroll
            for (int mt = 0; mt < 4; ++mt) {
                int r = wm + mt*16 + (lane >> 2);
                af[mt][0] = As[r][kk];     af[mt][1] = As[r+8][kk];
                af[mt][2] = As[r][kk+4];   af[mt][3] = As[r+8][kk+4];
            }
#pragma unroll
            for (int nt = 0; nt < 4; ++nt) {
                int n = wn + nt*8 + (lane >> 2);
                bf[nt][0] = Bs[n][kk];     bf[nt][1] = Bs[n][kk+4];
            }
#pragma unroll
            for (int mt = 0; mt < 4; ++mt)
#pragma unroll
                for (int nt = 0; nt < 4; ++nt)
                    mma_tf32(c[mt][nt], af[mt][0], af[mt][1], af[mt][2], af[mt][3],
                             bf[nt][0], bf[nt][1]);
        }
        __syncthreads();
    }
#pragma unroll
    for (int mt = 0; mt < 4; ++mt) {
#pragma unroll
        for (int nt = 0; nt < 4; ++nt) {
            int ncol = n0 + wn + nt*8 + 2*(lane & 3);
            float b0 = bo[ncol], b1 = bo[ncol+1];
            int mA = m0 + wm + mt*16 + (lane >> 2);
            float2 v0 = {c[mt][nt][0] + b0, c[mt][nt][1] + b1};
            *reinterpret_cast<float2*>(&out[(size_t)mA*HID + ncol]) = v0;
            float2 v1 = {c[mt][nt][2] + b0, c[mt][nt][3] + b1};
            *reinterpret_cast<float2*>(&out[(size_t)(mA+8)*HID + ncol]) = v1;
        }
    }
}

// ---------------- launch ----------------
extern "C" void kernel_launch(void* const* d_in, const int* in_sizes, int n_in,
                              void* d_out, int out_size)
{
    const float* query = (const float*)d_in[0];
    const float* key   = (const float*)d_in[1];
    const float* value = (const float*)d_in[2];
    const float* Wq = (const float*)d_in[3];  const float* bq = (const float*)d_in[4];
    const float* Wk = (const float*)d_in[5];  const float* bk = (const float*)d_in[6];
    const float* Wv = (const float*)d_in[7];  const float* bv = (const float*)d_in[8];
    const float* Wo = (const float*)d_in[9];  const float* bo = (const float*)d_in[10];
    const float* ent_w = (const float*)d_in[11];
    const float* ent_s = (const float*)d_in[12];
    const float* sup_w = (const float*)d_in[13];
    const float* sup_c = (const float*)d_in[14];

    float* out  = (float*)d_out;                 // [B,S,HID]
    float* attn = (float*)d_out + OUT_ELEMS;     // [B,NH,S,S]
    (void)in_sizes; (void)n_in; (void)out_size;

    static bool attr_set = false;
    if (!attr_set) {
        cudaFuncSetAttribute(flash_kernel,
                             cudaFuncAttributeMaxDynamicSharedMemorySize,
                             FL_SMEM_BYTES);
        attr_set = true;
    }

    // 1) composite 64x64 transforms
    build_T_kernel<<<1, 128>>>(ent_w, ent_s, sup_w, sup_c);

    // 2) fold transforms into projection weights
    dim3 tgrid(16, 16);
    transform_W_kernel<<<tgrid, 256>>>(Wq, bq, 0);
    transform_W_kernel<<<tgrid, 256>>>(Wk, bk, 1);
    transform_W_kernel<<<tgrid, 256>>>(Wv, bv, 2);

    // 3) projections (tf32 mma)
    dim3 pgrid(HID/128, MROWS/128);
    proj_mma_kernel<<<pgrid, 256>>>(query, 0);
    proj_mma_kernel<<<pgrid, 256>>>(key,   1);
    proj_mma_kernel<<<pgrid, 256>>>(value, 2);

    // 4) V transpose for the PV mma
    transpose_V_kernel<<<dim3(SEQ/32, HD/32, BH), dim3(32, 8)>>>();

    // 5) fused attention: probs -> attn (single write), context -> g_ctx
    flash_kernel<<<dim3(SEQ/128, BH), 256, FL_SMEM_BYTES>>>(attn);

    // 6) output projection (tf32 mma)
    dim3 ogrid(HID/128, MROWS/128);
    out_mma_kernel<<<ogrid, 256>>>(Wo, bo, out);
}

// round 10
// speedup vs baseline: 4.3649x; 1.1194x over previous
#include <cuda_runtime.h>
#include <cstdint>
#include <cstddef>

// Problem constants
#define BATCH 2
#define SEQ   2048
#define HID   1024
#define NH    16
#define HD    64
#define BH    (BATCH*NH)            // 32
#define MROWS (BATCH*SEQ)           // 4096
#define SCALE_ATT 0.125f            // 1/sqrt(64)
#define OUT_ELEMS ((size_t)BATCH*SEQ*HID)          // 4,194,304

// ---------------- device scratch (no allocs allowed) ----------------
__device__ float g_T[2][64*64];                 // 0: T for Q/K, 1: T for V
__device__ float g_Wt[3][HID*HID];              // transformed Wq,Wk,Wv
__device__ float g_bt[3][HID];
__device__ float g_QKV[2][(size_t)BH*SEQ*HD];   // Qq,Kq  [B,NH,S,D]
__device__ float g_Vt[(size_t)BH*HD*SEQ];       // Vq transposed [bh][d][s]
__device__ float g_ctx[(size_t)MROWS*HID];      // context   [B,S,HID]

// ---------------- tf32 mma helpers ----------------
__device__ __forceinline__ uint32_t f2tf32(float f) {
    uint32_t r;
    asm("cvt.rna.tf32.f32 %0, %1;" : "=r"(r) : "f"(f));
    return r;
}
__device__ __forceinline__ void mma_tf32(float c[4],
                                         uint32_t a0, uint32_t a1, uint32_t a2, uint32_t a3,
                                         uint32_t b0, uint32_t b1) {
    asm volatile(
        "mma.sync.aligned.m16n8k8.row.col.f32.tf32.tf32.f32 "
        "{%0,%1,%2,%3}, {%4,%5,%6,%7}, {%8,%9}, {%0,%1,%2,%3};"
        : "+f"(c[0]), "+f"(c[1]), "+f"(c[2]), "+f"(c[3])
        : "r"(a0), "r"(a1), "r"(a2), "r"(a3), "r"(b0), "r"(b1));
}

// ---------------- 1) build the 64x64 composite transforms ----------------
__global__ void build_T_kernel(const float* __restrict__ ent_w,  // [4,16,16]
                               const float* __restrict__ ent_s,  // [4]
                               const float* __restrict__ sup_w,  // [8,64]
                               const float* __restrict__ sup_c)  // [8]
{
    int t = threadIdx.x;
    if (t >= 128) return;
    int v = t >> 6;      // 0: QK path, 1: V path
    int i = t & 63;

    float x[64];
#pragma unroll
    for (int j = 0; j < 64; ++j) x[j] = (j == i) ? 1.0f : 0.0f;

    float w[64];
    for (int p = 0; p < 4; ++p)
        for (int j = 0; j < 16; ++j) {
            float acc = 0.f;
            for (int ii = 0; ii < 16; ++ii)
                acc += x[p*16 + ii] * ent_w[p*256 + ii*16 + j];
            w[p*16 + j] = acc;
        }
    for (int g = 0; g < 16; ++g) {
        float sc = ent_s[g >> 2];
        x[4*g+0] = w[4*g+0]*sc;
        x[4*g+1] = w[4*g+1]*sc;
        x[4*g+2] = w[4*g+3]*sc;
        x[4*g+3] = w[4*g+2]*sc;
    }
    const float R = 0.70710678118654752440f;
    for (int pr = 0; pr < 32; ++pr) {
        float a = x[2*pr], b = x[2*pr+1];
        x[2*pr]   = (a + b) * R;
        x[2*pr+1] = (a - b) * R;
    }
    for (int d = 0; d < 64; ++d) {
        float s = 0.f;
        for (int n = 0; n < 8; ++n) s += sup_c[n] * sup_w[n*64 + d];
        x[d] *= s;
    }
    if (v == 0) {
        for (int pr = 0; pr < 32; ++pr) {
            float a = x[2*pr], b = x[2*pr+1];
            x[2*pr]   = (a + b) * R;
            x[2*pr+1] = (a - b) * R;
        }
    } else {
        for (int g = 0; g < 16; ++g) {
            float a = x[4*g+2];
            x[4*g+2] = x[4*g+3];
            x[4*g+3] = a;
        }
    }
#pragma unroll
    for (int j = 0; j < 64; ++j) g_T[v][i*64 + j] = x[j];
}

// ---------------- 2) fold T into projection weights (smem-tiled) ----------
__global__ void transform_W_kernel(const float* __restrict__ W,
                                   const float* __restrict__ bvec,
                                   int mat)
{
    __shared__ float Ts[64][65];
    __shared__ float Ws[64][65];
    const float* __restrict__ T = g_T[(mat == 2) ? 1 : 0];
    const int head = blockIdx.y;
    const int k0 = blockIdx.x * 64;
    const int tid = threadIdx.x;

#pragma unroll
    for (int l = 0; l < 16; ++l) {
        int idx = tid + l*256;
        int i = idx >> 6, c = idx & 63;
        Ts[i][c] = T[idx];
        Ws[i][c] = W[(size_t)(head*64 + i)*HID + k0 + c];
    }
    __syncthreads();

    const int k = tid & 63, g = tid >> 6;   // g in 0..3, 16 ml values each
    float acc[16] = {};
    for (int i = 0; i < 64; ++i) {
        float wv = Ws[i][k];
#pragma unroll
        for (int j = 0; j < 16; ++j)
            acc[j] += Ts[i][g*16 + j] * wv;
    }
#pragma unroll
    for (int j = 0; j < 16; ++j)
        g_Wt[mat][(size_t)(head*64 + g*16 + j)*HID + k0 + k] = acc[j];

    if (blockIdx.x == 0 && tid < 64) {
        float ab = 0.f;
        for (int i = 0; i < 64; ++i)
            ab += Ts[i][tid] * bvec[head*64 + i];
        g_bt[mat][head*64 + tid] = ab;
    }
}

// ---------------- 3) projection: C = A * W'^T + b' ------
// mat 0/1 -> g_QKV[mat] [B,NH,S,D];  mat 2 -> g_Vt [bh][d][s] (transposed)
__global__ void proj_mma_kernel(const float* __restrict__ A, int mat)
{
    __shared__ uint32_t As[128][20];
    __shared__ uint32_t Bs[128][20];
    const float* __restrict__ Wm = g_Wt[mat];
    const float* __restrict__ bm = g_bt[mat];

    const int m0 = blockIdx.y * 128, n0 = blockIdx.x * 128;
    const int tid = threadIdx.x, lane = tid & 31, warp = tid >> 5;
    const int wm = (warp & 1) * 64, wn = (warp >> 1) * 32;

    float c[4][4][4];
#pragma unroll
    for (int a = 0; a < 4; ++a)
#pragma unroll
        for (int b = 0; b < 4; ++b)
#pragma unroll
            for (int d = 0; d < 4; ++d) c[a][b][d] = 0.f;

    for (int k0 = 0; k0 < HID; k0 += 16) {
#pragma unroll
        for (int l = 0; l < 2; ++l) {
            int idx = tid + l*256;
            int r = idx >> 2, c4 = (idx & 3) * 4;
            float4 va = *reinterpret_cast<const float4*>(&A[(size_t)(m0 + r)*HID + k0 + c4]);
            As[r][c4+0] = f2tf32(va.x); As[r][c4+1] = f2tf32(va.y);
            As[r][c4+2] = f2tf32(va.z); As[r][c4+3] = f2tf32(va.w);
            float4 vb = *reinterpret_cast<const float4*>(&Wm[(size_t)(n0 + r)*HID + k0 + c4]);
            Bs[r][c4+0] = f2tf32(vb.x); Bs[r][c4+1] = f2tf32(vb.y);
            Bs[r][c4+2] = f2tf32(vb.z); Bs[r][c4+3] = f2tf32(vb.w);
        }
        __syncthreads();
#pragma unroll
        for (int mi = 0; mi < 2; ++mi) {
            const int kk = mi*8 + (lane & 3);
            uint32_t af[4][4], bf[4][2];
#pragma unroll
            for (int mt = 0; mt < 4; ++mt) {
                int r = wm + mt*16 + (lane >> 2);
                af[mt][0] = As[r][kk];     af[mt][1] = As[r+8][kk];
                af[mt][2] = As[r][kk+4];   af[mt][3] = As[r+8][kk+4];
            }
#pragma unroll
            for (int nt = 0; nt < 4; ++nt) {
                int n = wn + nt*8 + (lane >> 2);
                bf[nt][0] = Bs[n][kk];     bf[nt][1] = Bs[n][kk+4];
            }
#pragma unroll
            for (int mt = 0; mt < 4; ++mt)
#pragma unroll
                for (int nt = 0; nt < 4; ++nt)
                    mma_tf32(c[mt][nt], af[mt][0], af[mt][1], af[mt][2], af[mt][3],
                             bf[nt][0], bf[nt][1]);
        }
        __syncthreads();
    }
    if (mat == 2) {
        // write V transposed: g_Vt[(bi*NH+h)*HD + d][s]
#pragma unroll
        for (int mt = 0; mt < 4; ++mt) {
#pragma unroll
            for (int nt = 0; nt < 4; ++nt) {
                int ncol = n0 + wn + nt*8 + 2*(lane & 3);
                int h = ncol >> 6, d = ncol & 63;
                float b0 = bm[ncol], b1 = bm[ncol+1];
                int mA = m0 + wm + mt*16 + (lane >> 2);
                {
                    int bi = mA >> 11, s = mA & 2047;
                    size_t base = ((size_t)(bi*NH + h)*HD + d)*SEQ + s;
                    g_Vt[base]       = c[mt][nt][0] + b0;
                    g_Vt[base + SEQ] = c[mt][nt][1] + b1;
                }
                {
                    int mB = mA + 8;
                    int bi = mB >> 11, s = mB & 2047;
                    size_t base = ((size_t)(bi*NH + h)*HD + d)*SEQ + s;
                    g_Vt[base]       = c[mt][nt][2] + b0;
                    g_Vt[base + SEQ] = c[mt][nt][3] + b1;
                }
            }
        }
    } else {
        float* __restrict__ Cdst = g_QKV[mat];
#pragma unroll
        for (int mt = 0; mt < 4; ++mt) {
#pragma unroll
            for (int nt = 0; nt < 4; ++nt) {
                int ncol = n0 + wn + nt*8 + 2*(lane & 3);
                int h = ncol >> 6, d = ncol & 63;
                float b0 = bm[ncol], b1 = bm[ncol+1];
                int mA = m0 + wm + mt*16 + (lane >> 2);
                {
                    int bi = mA >> 11, s = mA & 2047;
                    float2 v = {c[mt][nt][0] + b0, c[mt][nt][1] + b1};
                    *reinterpret_cast<float2*>(&Cdst[(((size_t)bi*NH + h)*SEQ + s)*HD + d]) = v;
                }
                {
                    int mB = mA + 8;
                    int bi = mB >> 11, s = mB & 2047;
                    float2 v = {c[mt][nt][2] + b0, c[mt][nt][3] + b1};
                    *reinterpret_cast<float2*>(&Cdst[(((size_t)bi*NH + h)*SEQ + s)*HD + d]) = v;
                }
            }
        }
    }
}

// ---------------- 4) flash attention, rows-per-warp ------------------------
// grid (SEQ/128=16, BH=32), 256 threads. Each warp owns 16 rows x full 128 cols
// of every S tile -> softmax stats stay in registers; P stays in registers and
// is converted C-frag -> A-frag by quad shuffles (no Ps smem).
// smem: Qs[128][68] + Ks[128][68] + Vs[64][132]  (tf32)  = 103424 B
#define FQ_OFF 0
#define FK_OFF (128*68)
#define FV_OFF (2*128*68)
#define FL_SMEM_BYTES ((2*128*68 + 64*132) * 4)

__global__ void __launch_bounds__(256, 1) flash_kernel(float* __restrict__ attn)
{
    extern __shared__ uint32_t sm[];
    uint32_t (*Qs)[68]  = reinterpret_cast<uint32_t(*)[68]>(sm + FQ_OFF);
    uint32_t (*Ks)[68]  = reinterpret_cast<uint32_t(*)[68]>(sm + FK_OFF);
    uint32_t (*Vs)[132] = reinterpret_cast<uint32_t(*)[132]>(sm + FV_OFF);

    const int z  = blockIdx.y;
    const int m0 = blockIdx.x * 128;
    const float* __restrict__ Qg  = g_QKV[0] + (size_t)z*SEQ*HD;
    const float* __restrict__ Kg  = g_QKV[1] + (size_t)z*SEQ*HD;
    const float* __restrict__ Vtg = g_Vt     + (size_t)z*HD*SEQ;
    float* __restrict__ Cz = attn + (size_t)z*SEQ*SEQ;

    const int tid = threadIdx.x, lane = tid & 31, warp = tid >> 5;
    const int g = lane >> 2, l = lane & 3;
    const int ra = warp*16 + g;           // this thread's row (and ra+8)

    // ---- stage Q tile once (scaled by SCALE_ATT) ----
#pragma unroll
    for (int l8 = 0; l8 < 8; ++l8) {
        int idx = tid + l8*256;
        int r = idx >> 4, c4 = (idx & 15) * 4;
        float4 v = *reinterpret_cast<const float4*>(&Qg[(size_t)(m0 + r)*HD + c4]);
        Qs[r][c4+0] = f2tf32(v.x * SCALE_ATT);
        Qs[r][c4+1] = f2tf32(v.y * SCALE_ATT);
        Qs[r][c4+2] = f2tf32(v.z * SCALE_ATT);
        Qs[r][c4+3] = f2tf32(v.w * SCALE_ATT);
    }

    // prefetch K(0)
    float4 kreg[8];
#pragma unroll
    for (int l8 = 0; l8 < 8; ++l8) {
        int idx = tid + l8*256;
        int r = idx >> 4, c4 = (idx & 15) * 4;
        kreg[l8] = *reinterpret_cast<const float4*>(&Kg[(size_t)r*HD + c4]);
    }

    float M0 = -3.0e38f, M1 = -3.0e38f, S0 = 0.f, S1 = 0.f;

    // ================= pass 1: row max + sumexp (register stats) ==========
    for (int j = 0; j < 16; ++j) {
#pragma unroll
        for (int l8 = 0; l8 < 8; ++l8) {
            int idx = tid + l8*256;
            int r = idx >> 4, c4 = (idx & 15) * 4;
            Ks[r][c4+0] = f2tf32(kreg[l8].x); Ks[r][c4+1] = f2tf32(kreg[l8].y);
            Ks[r][c4+2] = f2tf32(kreg[l8].z); Ks[r][c4+3] = f2tf32(kreg[l8].w);
        }
        __syncthreads();
        if (j < 15) {
#pragma unroll
            for (int l8 = 0; l8 < 8; ++l8) {
                int idx = tid + l8*256;
                int r = idx >> 4, c4 = (idx & 15) * 4;
                kreg[l8] = *reinterpret_cast<const float4*>(&Kg[(size_t)((j+1)*128 + r)*HD + c4]);
            }
        }

        float cs[16][4];
#pragma unroll
        for (int nt = 0; nt < 16; ++nt)
#pragma unroll
            for (int d = 0; d < 4; ++d) cs[nt][d] = 0.f;

#pragma unroll
        for (int ks = 0; ks < 8; ++ks) {
            const int kk = ks*8 + l;
            uint32_t a0 = Qs[ra][kk],   a1 = Qs[ra+8][kk];
            uint32_t a2 = Qs[ra][kk+4], a3 = Qs[ra+8][kk+4];
#pragma unroll
            for (int nt = 0; nt < 16; ++nt) {
                uint32_t b0 = Ks[nt*8 + g][kk], b1 = Ks[nt*8 + g][kk+4];
                mma_tf32(cs[nt], a0, a1, a2, a3, b0, b1);
            }
        }

        // tile row max (quad shuffles)
        float t0 = -3.0e38f, t1 = -3.0e38f;
#pragma unroll
        for (int nt = 0; nt < 16; ++nt) {
            t0 = fmaxf(t0, fmaxf(cs[nt][0], cs[nt][1]));
            t1 = fmaxf(t1, fmaxf(cs[nt][2], cs[nt][3]));
        }
        t0 = fmaxf(t0, __shfl_xor_sync(0xffffffffu, t0, 1));
        t0 = fmaxf(t0, __shfl_xor_sync(0xffffffffu, t0, 2));
        t1 = fmaxf(t1, __shfl_xor_sync(0xffffffffu, t1, 1));
        t1 = fmaxf(t1, __shfl_xor_sync(0xffffffffu, t1, 2));

        float e0 = 0.f, e1 = 0.f;
#pragma unroll
        for (int nt = 0; nt < 16; ++nt) {
            e0 += __expf(cs[nt][0] - t0) + __expf(cs[nt][1] - t0);
            e1 += __expf(cs[nt][2] - t1) + __expf(cs[nt][3] - t1);
        }
        e0 += __shfl_xor_sync(0xffffffffu, e0, 1);
        e0 += __shfl_xor_sync(0xffffffffu, e0, 2);
        e1 += __shfl_xor_sync(0xffffffffu, e1, 1);
        e1 += __shfl_xor_sync(0xffffffffu, e1, 2);

        float mn0 = fmaxf(M0, t0);
        S0 = S0*__expf(M0 - mn0) + e0*__expf(t0 - mn0);  M0 = mn0;
        float mn1 = fmaxf(M1, t1);
        S1 = S1*__expf(M1 - mn1) + e1*__expf(t1 - mn1);  M1 = mn1;
        __syncthreads();
    }

    const float I0 = 1.0f / S0, I1 = 1.0f / S1;

    float co[8][4];
#pragma unroll
    for (int a = 0; a < 8; ++a)
#pragma unroll
        for (int d = 0; d < 4; ++d) co[a][d] = 0.f;

    // prefetch K(0), V(0) for pass 2
    float4 vreg[8];
#pragma unroll
    for (int l8 = 0; l8 < 8; ++l8) {
        int idx = tid + l8*256;
        int r = idx >> 4, c4 = (idx & 15) * 4;
        kreg[l8] = *reinterpret_cast<const float4*>(&Kg[(size_t)r*HD + c4]);
        int d = idx >> 5, s4 = (idx & 31) * 4;
        vreg[l8] = *reinterpret_cast<const float4*>(&Vtg[(size_t)d*SEQ + s4]);
    }

    const int qbase = lane & 28;          // quad base lane
    const int src0  = qbase + (l >> 1);   // frag-convert source lanes
    const int src1  = src0 + 2;
    const int lodd  = l & 1;

    // ================= pass 2: probs -> attn, P*V -> ctx =================
    for (int j = 0; j < 16; ++j) {
#pragma unroll
        for (int l8 = 0; l8 < 8; ++l8) {
            int idx = tid + l8*256;
            int r = idx >> 4, c4 = (idx & 15) * 4;
            Ks[r][c4+0] = f2tf32(kreg[l8].x); Ks[r][c4+1] = f2tf32(kreg[l8].y);
            Ks[r][c4+2] = f2tf32(kreg[l8].z); Ks[r][c4+3] = f2tf32(kreg[l8].w);
            int d = idx >> 5, s4 = (idx & 31) * 4;
            Vs[d][s4+0] = f2tf32(vreg[l8].x); Vs[d][s4+1] = f2tf32(vreg[l8].y);
            Vs[d][s4+2] = f2tf32(vreg[l8].z); Vs[d][s4+3] = f2tf32(vreg[l8].w);
        }
        __syncthreads();
        if (j < 15) {
#pragma unroll
            for (int l8 = 0; l8 < 8; ++l8) {
                int idx = tid + l8*256;
                int r = idx >> 4, c4 = (idx & 15) * 4;
                kreg[l8] = *reinterpret_cast<const float4*>(&Kg[(size_t)((j+1)*128 + r)*HD + c4]);
                int d = idx >> 5, s4 = (idx & 31) * 4;
                vreg[l8] = *reinterpret_cast<const float4*>(&Vtg[(size_t)d*SEQ + (j+1)*128 + s4]);
            }
        }

        // recompute S tile
        float cs[16][4];
#pragma unroll
        for (int nt = 0; nt < 16; ++nt)
#pragma unroll
            for (int d = 0; d < 4; ++d) cs[nt][d] = 0.f;
#pragma unroll
        for (int ks = 0; ks < 8; ++ks) {
            const int kk = ks*8 + l;
            uint32_t a0 = Qs[ra][kk],   a1 = Qs[ra+8][kk];
            uint32_t a2 = Qs[ra][kk+4], a3 = Qs[ra+8][kk+4];
#pragma unroll
            for (int nt = 0; nt < 16; ++nt) {
                uint32_t b0 = Ks[nt*8 + g][kk], b1 = Ks[nt*8 + g][kk+4];
                mma_tf32(cs[nt], a0, a1, a2, a3, b0, b1);
            }
        }

        // per 8-col block: probs -> attn, frag convert, PV MMA (k-step = nt)
#pragma unroll
        for (int nt = 0; nt < 16; ++nt) {
            float p0 = __expf(cs[nt][0] - M0) * I0;
            float p1 = __expf(cs[nt][1] - M0) * I0;
            float p2 = __expf(cs[nt][2] - M1) * I1;
            float p3 = __expf(cs[nt][3] - M1) * I1;

            int colg = j*128 + nt*8 + 2*l;
            float2 v0 = {p0, p1};
            *reinterpret_cast<float2*>(&Cz[(size_t)(m0 + ra)*SEQ + colg]) = v0;
            float2 v1 = {p2, p3};
            *reinterpret_cast<float2*>(&Cz[(size_t)(m0 + ra + 8)*SEQ + colg]) = v1;

            uint32_t ct0 = f2tf32(p0), ct1 = f2tf32(p1);
            uint32_t ct2 = f2tf32(p2), ct3 = f2tf32(p3);

            // C-frag -> A-frag via quad shuffles
            uint32_t u0 = __shfl_sync(0xffffffffu, ct0, src0);
            uint32_t u1 = __shfl_sync(0xffffffffu, ct1, src0);
            uint32_t a0 = lodd ? u1 : u0;
            uint32_t u2 = __shfl_sync(0xffffffffu, ct2, src0);
            uint32_t u3 = __shfl_sync(0xffffffffu, ct3, src0);
            uint32_t a1 = lodd ? u3 : u2;
            uint32_t u4 = __shfl_sync(0xffffffffu, ct0, src1);
            uint32_t u5 = __shfl_sync(0xffffffffu, ct1, src1);
            uint32_t a2 = lodd ? u5 : u4;
            uint32_t u6 = __shfl_sync(0xffffffffu, ct2, src1);
            uint32_t u7 = __shfl_sync(0xffffffffu, ct3, src1);
            uint32_t a3 = lodd ? u7 : u6;

            const int kk2 = nt*8 + l;
#pragma unroll
            for (int no = 0; no < 8; ++no) {
                uint32_t b0 = Vs[no*8 + g][kk2], b1 = Vs[no*8 + g][kk2+4];
                mma_tf32(co[no], a0, a1, a2, a3, b0, b1);
            }
        }
        __syncthreads();
    }

    // epilogue: context to g_ctx [B,S,HID]
    const int bi = z >> 4, h = z & 15;
#pragma unroll
    for (int no = 0; no < 8; ++no) {
        int d = no*8 + 2*l;
        int q = m0 + ra;
        float2 v0 = {co[no][0], co[no][1]};
        *reinterpret_cast<float2*>(&g_ctx[((size_t)bi*SEQ + q)*HID + (h<<6) + d]) = v0;
        float2 v1 = {co[no][2], co[no][3]};
        *reinterpret_cast<float2*>(&g_ctx[((size_t)bi*SEQ + q + 8)*HID + (h<<6) + d]) = v1;
    }
}

// ---------------- 5) output = ctx @ Wo^T + bo ----------------
__global__ void out_mma_kernel(const float* __restrict__ Wo,
                               const float* __restrict__ bo,
                               float* __restrict__ out)
{
    __shared__ uint32_t As[128][20];
    __shared__ uint32_t Bs[128][20];
    const int m0 = blockIdx.y * 128, n0 = blockIdx.x * 128;
    const int tid = threadIdx.x, lane = tid & 31, warp = tid >> 5;
    const int wm = (warp & 1) * 64, wn = (warp >> 1) * 32;

    float c[4][4][4];
#pragma unroll
    for (int a = 0; a < 4; ++a)
#pragma unroll
        for (int b = 0; b < 4; ++b)
#pragma unroll
            for (int d = 0; d < 4; ++d) c[a][b][d] = 0.f;

    for (int k0 = 0; k0 < HID; k0 += 16) {
#pragma unroll
        for (int l = 0; l < 2; ++l) {
            int idx = tid + l*256;
            int r = idx >> 2, c4 = (idx & 3) * 4;
            float4 va = *reinterpret_cast<const float4*>(&g_ctx[(size_t)(m0 + r)*HID + k0 + c4]);
            As[r][c4+0] = f2tf32(va.x); As[r][c4+1] = f2tf32(va.y);
            As[r][c4+2] = f2tf32(va.z); As[r][c4+3] = f2tf32(va.w);
            float4 vb = *reinterpret_cast<const float4*>(&Wo[(size_t)(n0 + r)*HID + k0 + c4]);
            Bs[r][c4+0] = f2tf32(vb.x); Bs[r][c4+1] = f2tf32(vb.y);
            Bs[r][c4+2] = f2tf32(vb.z); Bs[r][c4+3] = f2tf32(vb.w);
        }
        __syncthreads();
#pragma unroll
        for (int mi = 0; mi < 2; ++mi) {
            const int kk = mi*8 + (lane & 3);
            uint32_t af[4][4], bf[4][2];
#pragma unroll
            for (int mt = 0; mt < 4; ++mt) {
                int r = wm + mt*16 + (lane >> 2);
                af[mt][0] = As[r][kk];     af[mt][1] = As[r+8][kk];
                af[mt][2] = As[r][kk+4];   af[mt][3] = As[r+8][kk+4];
            }
#pragma unroll
            for (int nt = 0; nt < 4; ++nt) {
                int n = wn + nt*8 + (lane >> 2);
                bf[nt][0] = Bs[n][kk];     bf[nt][1] = Bs[n][kk+4];
            }
#pragma unroll
            for (int mt = 0; mt < 4; ++mt)
#pragma unroll
                for (int nt = 0; nt < 4; ++nt)
                    mma_tf32(c[mt][nt], af[mt][0], af[mt][1], af[mt][2], af[mt][3],
                             bf[nt][0], bf[nt][1]);
        }
        __syncthreads();
    }
#pragma unroll
    for (int mt = 0; mt < 4; ++mt) {
#pragma unroll
        for (int nt = 0; nt < 4; ++nt) {
            int ncol = n0 + wn + nt*8 + 2*(lane & 3);
            float b0 = bo[ncol], b1 = bo[ncol+1];
            int mA = m0 + wm + mt*16 + (lane >> 2);
            float2 v0 = {c[mt][nt][0] + b0, c[mt][nt][1] + b1};
            *reinterpret_cast<float2*>(&out[(size_t)mA*HID + ncol]) = v0;
            float2 v1 = {c[mt][nt][2] + b0, c[mt][nt][3] + b1};
            *reinterpret_cast<float2*>(&out[(size_t)(mA+8)*HID + ncol]) = v1;
        }
    }
}

// ---------------- launch ----------------
extern "C" void kernel_launch(void* const* d_in, const int* in_sizes, int n_in,
                              void* d_out, int out_size)
{
    const float* query = (const float*)d_in[0];
    const float* key   = (const float*)d_in[1];
    const float* value = (const float*)d_in[2];
    const float* Wq = (const float*)d_in[3];  const float* bq = (const float*)d_in[4];
    const float* Wk = (const float*)d_in[5];  const float* bk = (const float*)d_in[6];
    const float* Wv = (const float*)d_in[7];  const float* bv = (const float*)d_in[8];
    const float* Wo = (const float*)d_in[9];  const float* bo = (const float*)d_in[10];
    const float* ent_w = (const float*)d_in[11];
    const float* ent_s = (const float*)d_in[12];
    const float* sup_w = (const float*)d_in[13];
    const float* sup_c = (const float*)d_in[14];

    float* out  = (float*)d_out;                 // [B,S,HID]
    float* attn = (float*)d_out + OUT_ELEMS;     // [B,NH,S,S]
    (void)in_sizes; (void)n_in; (void)out_size;

    static bool attr_set = false;
    if (!attr_set) {
        cudaFuncSetAttribute(flash_kernel,
                             cudaFuncAttributeMaxDynamicSharedMemorySize,
                             FL_SMEM_BYTES);
        attr_set = true;
    }

    // 1) composite 64x64 transforms
    build_T_kernel<<<1, 128>>>(ent_w, ent_s, sup_w, sup_c);

    // 2) fold transforms into projection weights
    dim3 tgrid(16, 16);
    transform_W_kernel<<<tgrid, 256>>>(Wq, bq, 0);
    transform_W_kernel<<<tgrid, 256>>>(Wk, bk, 1);
    transform_W_kernel<<<tgrid, 256>>>(Wv, bv, 2);

    // 3) projections (tf32 mma); V written pre-transposed
    dim3 pgrid(HID/128, MROWS/128);
    proj_mma_kernel<<<pgrid, 256>>>(query, 0);
    proj_mma_kernel<<<pgrid, 256>>>(key,   1);
    proj_mma_kernel<<<pgrid, 256>>>(value, 2);

    // 4) fused attention: probs -> attn (single write), context -> g_ctx
    flash_kernel<<<dim3(SEQ/128, BH), 256, FL_SMEM_BYTES>>>(attn);

    // 5) output projection (tf32 mma)
    dim3 ogrid(HID/128, MROWS/128);
    out_mma_kernel<<<ogrid, 256>>>(Wo, bo, out);
}

// round 11
// speedup vs baseline: 6.6550x; 1.5247x over previous
#include <cuda_runtime.h>
#include <cuda_bf16.h>
#include <cstdint>
#include <cstddef>

// Problem constants
#define BATCH 2
#define SEQ   2048
#define HID   1024
#define NH    16
#define HD    64
#define BH    (BATCH*NH)            // 32
#define MROWS (BATCH*SEQ)           // 4096
#define SCALE_ATT 0.125f            // 1/sqrt(64)
#define OUT_ELEMS ((size_t)BATCH*SEQ*HID)          // 4,194,304

// ---------------- device scratch (no allocs allowed) ----------------
__device__ float g_T[2][64*64];                 // 0: T for Q/K, 1: T for V
__device__ float g_Wt[3][HID*HID];              // transformed Wq,Wk,Wv
__device__ float g_bt[3][HID];
__device__ float g_QKV[2][(size_t)BH*SEQ*HD];   // Qq,Kq  [B,NH,S,D]
__device__ float g_Vt[(size_t)BH*HD*SEQ];       // Vq transposed [bh][d][s]
__device__ float g_ctx[(size_t)MROWS*HID];      // context   [B,S,HID]

// ---------------- bf16 mma helpers ----------------
// pack two floats -> bf16x2 register, lo = first (smaller k index)
__device__ __forceinline__ uint32_t pbf(float lo, float hi) {
    uint32_t r;
    asm("cvt.rn.bf16x2.f32 %0, %1, %2;" : "=r"(r) : "f"(hi), "f"(lo));
    return r;
}
__device__ __forceinline__ void mma_bf16(float c[4],
                                         uint32_t a0, uint32_t a1, uint32_t a2, uint32_t a3,
                                         uint32_t b0, uint32_t b1) {
    asm volatile(
        "mma.sync.aligned.m16n8k16.row.col.f32.bf16.bf16.f32 "
        "{%0,%1,%2,%3}, {%4,%5,%6,%7}, {%8,%9}, {%0,%1,%2,%3};"
        : "+f"(c[0]), "+f"(c[1]), "+f"(c[2]), "+f"(c[3])
        : "r"(a0), "r"(a1), "r"(a2), "r"(a3), "r"(b0), "r"(b1));
}

// ---------------- 1) build the 64x64 composite transforms ----------------
__global__ void build_T_kernel(const float* __restrict__ ent_w,  // [4,16,16]
                               const float* __restrict__ ent_s,  // [4]
                               const float* __restrict__ sup_w,  // [8,64]
                               const float* __restrict__ sup_c)  // [8]
{
    int t = threadIdx.x;
    if (t >= 128) return;
    int v = t >> 6;      // 0: QK path, 1: V path
    int i = t & 63;

    float x[64];
#pragma unroll
    for (int j = 0; j < 64; ++j) x[j] = (j == i) ? 1.0f : 0.0f;

    float w[64];
    for (int p = 0; p < 4; ++p)
        for (int j = 0; j < 16; ++j) {
            float acc = 0.f;
            for (int ii = 0; ii < 16; ++ii)
                acc += x[p*16 + ii] * ent_w[p*256 + ii*16 + j];
            w[p*16 + j] = acc;
        }
    for (int g = 0; g < 16; ++g) {
        float sc = ent_s[g >> 2];
        x[4*g+0] = w[4*g+0]*sc;
        x[4*g+1] = w[4*g+1]*sc;
        x[4*g+2] = w[4*g+3]*sc;
        x[4*g+3] = w[4*g+2]*sc;
    }
    const float R = 0.70710678118654752440f;
    for (int pr = 0; pr < 32; ++pr) {
        float a = x[2*pr], b = x[2*pr+1];
        x[2*pr]   = (a + b) * R;
        x[2*pr+1] = (a - b) * R;
    }
    for (int d = 0; d < 64; ++d) {
        float s = 0.f;
        for (int n = 0; n < 8; ++n) s += sup_c[n] * sup_w[n*64 + d];
        x[d] *= s;
    }
    if (v == 0) {
        for (int pr = 0; pr < 32; ++pr) {
            float a = x[2*pr], b = x[2*pr+1];
            x[2*pr]   = (a + b) * R;
            x[2*pr+1] = (a - b) * R;
        }
    } else {
        for (int g = 0; g < 16; ++g) {
            float a = x[4*g+2];
            x[4*g+2] = x[4*g+3];
            x[4*g+3] = a;
        }
    }
#pragma unroll
    for (int j = 0; j < 64; ++j) g_T[v][i*64 + j] = x[j];
}

// ---------------- 2) fold T into projection weights (merged 3 mats) -------
// grid (16 kblocks, 16 heads, 3 mats), 256 threads
__global__ void transform_W_kernel(const float* __restrict__ Wq, const float* __restrict__ bq,
                                   const float* __restrict__ Wk, const float* __restrict__ bk,
                                   const float* __restrict__ Wv, const float* __restrict__ bv)
{
    __shared__ float Ts[64][65];
    __shared__ float Ws[64][65];
    const int mat = blockIdx.z;
    const float* __restrict__ W    = (mat == 0) ? Wq : (mat == 1) ? Wk : Wv;
    const float* __restrict__ bvec = (mat == 0) ? bq : (mat == 1) ? bk : bv;
    const float* __restrict__ T = g_T[(mat == 2) ? 1 : 0];
    const int head = blockIdx.y;
    const int k0 = blockIdx.x * 64;
    const int tid = threadIdx.x;

#pragma unroll
    for (int l = 0; l < 16; ++l) {
        int idx = tid + l*256;
        int i = idx >> 6, c = idx & 63;
        Ts[i][c] = T[idx];
        Ws[i][c] = W[(size_t)(head*64 + i)*HID + k0 + c];
    }
    __syncthreads();

    const int k = tid & 63, g = tid >> 6;   // g in 0..3, 16 ml values each
    float acc[16] = {};
    for (int i = 0; i < 64; ++i) {
        float wv = Ws[i][k];
#pragma unroll
        for (int j = 0; j < 16; ++j)
            acc[j] += Ts[i][g*16 + j] * wv;
    }
#pragma unroll
    for (int j = 0; j < 16; ++j)
        g_Wt[mat][(size_t)(head*64 + g*16 + j)*HID + k0 + k] = acc[j];

    if (blockIdx.x == 0 && tid < 64) {
        float ab = 0.f;
        for (int i = 0; i < 64; ++i)
            ab += Ts[i][tid] * bvec[head*64 + i];
        g_bt[mat][head*64 + tid] = ab;
    }
}

// ---------------- 3) projections (bf16 mma, merged 3 mats) -----------------
// grid (HID/128=8, MROWS/128=32, 3), 256 threads. k-chunk 32.
// mat 0/1 -> g_QKV[mat] [B,NH,S,D];  mat 2 -> g_Vt [bh][d][s] (transposed)
__global__ void proj_mma_kernel(const float* __restrict__ Aq,
                                const float* __restrict__ Ak,
                                const float* __restrict__ Av)
{
    __shared__ uint32_t As[128][20];
    __shared__ uint32_t Bs[128][20];
    const int mat = blockIdx.z;
    const float* __restrict__ A  = (mat == 0) ? Aq : (mat == 1) ? Ak : Av;
    const float* __restrict__ Wm = g_Wt[mat];
    const float* __restrict__ bm = g_bt[mat];

    const int m0 = blockIdx.y * 128, n0 = blockIdx.x * 128;
    const int tid = threadIdx.x, lane = tid & 31, warp = tid >> 5;
    const int wm = (warp & 1) * 64, wn = (warp >> 1) * 32;
    const int g = lane >> 2, l = lane & 3;

    float c[4][4][4];
#pragma unroll
    for (int a = 0; a < 4; ++a)
#pragma unroll
        for (int b = 0; b < 4; ++b)
#pragma unroll
            for (int d = 0; d < 4; ++d) c[a][b][d] = 0.f;

    for (int k0 = 0; k0 < HID; k0 += 32) {
#pragma unroll
        for (int it = 0; it < 2; ++it) {
            int idx = tid + it*256;
            int r = idx >> 2, c8 = idx & 3;
            const float* pa = &A[(size_t)(m0 + r)*HID + k0 + c8*8];
            float4 v0 = *reinterpret_cast<const float4*>(pa);
            float4 v1 = *reinterpret_cast<const float4*>(pa + 4);
            uint4 u = {pbf(v0.x, v0.y), pbf(v0.z, v0.w), pbf(v1.x, v1.y), pbf(v1.z, v1.w)};
            *reinterpret_cast<uint4*>(&As[r][c8*4]) = u;
            const float* pb = &Wm[(size_t)(n0 + r)*HID + k0 + c8*8];
            float4 w0 = *reinterpret_cast<const float4*>(pb);
            float4 w1 = *reinterpret_cast<const float4*>(pb + 4);
            uint4 ub = {pbf(w0.x, w0.y), pbf(w0.z, w0.w), pbf(w1.x, w1.y), pbf(w1.z, w1.w)};
            *reinterpret_cast<uint4*>(&Bs[r][c8*4]) = ub;
        }
        __syncthreads();
#pragma unroll
        for (int ks = 0; ks < 2; ++ks) {
            const int kk = ks*8 + l;
            uint32_t af[4][4], bf[4][2];
#pragma unroll
            for (int mt = 0; mt < 4; ++mt) {
                int r = wm + mt*16 + g;
                af[mt][0] = As[r][kk];     af[mt][1] = As[r+8][kk];
                af[mt][2] = As[r][kk+4];   af[mt][3] = As[r+8][kk+4];
            }
#pragma unroll
            for (int nt = 0; nt < 4; ++nt) {
                int n = wn + nt*8 + g;
                bf[nt][0] = Bs[n][kk];     bf[nt][1] = Bs[n][kk+4];
            }
#pragma unroll
            for (int mt = 0; mt < 4; ++mt)
#pragma unroll
                for (int nt = 0; nt < 4; ++nt)
                    mma_bf16(c[mt][nt], af[mt][0], af[mt][1], af[mt][2], af[mt][3],
                             bf[nt][0], bf[nt][1]);
        }
        __syncthreads();
    }
    if (mat == 2) {
        // write V transposed: g_Vt[(bi*NH+h)*HD + d][s]
#pragma unroll
        for (int mt = 0; mt < 4; ++mt) {
#pragma unroll
            for (int nt = 0; nt < 4; ++nt) {
                int ncol = n0 + wn + nt*8 + 2*l;
                int h = ncol >> 6, d = ncol & 63;
                float b0 = bm[ncol], b1 = bm[ncol+1];
                int mA = m0 + wm + mt*16 + g;
                {
                    int bi = mA >> 11, s = mA & 2047;
                    size_t base = ((size_t)(bi*NH + h)*HD + d)*SEQ + s;
                    g_Vt[base]       = c[mt][nt][0] + b0;
                    g_Vt[base + SEQ] = c[mt][nt][1] + b1;
                }
                {
                    int mB = mA + 8;
                    int bi = mB >> 11, s = mB & 2047;
                    size_t base = ((size_t)(bi*NH + h)*HD + d)*SEQ + s;
                    g_Vt[base]       = c[mt][nt][2] + b0;
                    g_Vt[base + SEQ] = c[mt][nt][3] + b1;
                }
            }
        }
    } else {
        float* __restrict__ Cdst = g_QKV[mat];
#pragma unroll
        for (int mt = 0; mt < 4; ++mt) {
#pragma unroll
            for (int nt = 0; nt < 4; ++nt) {
                int ncol = n0 + wn + nt*8 + 2*l;
                int h = ncol >> 6, d = ncol & 63;
                float b0 = bm[ncol], b1 = bm[ncol+1];
                int mA = m0 + wm + mt*16 + g;
                {
                    int bi = mA >> 11, s = mA & 2047;
                    float2 v = {c[mt][nt][0] + b0, c[mt][nt][1] + b1};
                    *reinterpret_cast<float2*>(&Cdst[(((size_t)bi*NH + h)*SEQ + s)*HD + d]) = v;
                }
                {
                    int mB = mA + 8;
                    int bi = mB >> 11, s = mB & 2047;
                    float2 v = {c[mt][nt][2] + b0, c[mt][nt][3] + b1};
                    *reinterpret_cast<float2*>(&Cdst[(((size_t)bi*NH + h)*SEQ + s)*HD + d]) = v;
                }
            }
        }
    }
}

// ---------------- 4) flash attention, rows-per-warp, bf16 ------------------
// grid (SEQ/128=16, BH=32), 256 threads. Each warp owns 16 rows x 128 cols.
// bf16 m16n8k16: P C-frag -> A-frag needs NO shuffles (same-thread repack).
// smem (uint32): Qs[128][36] + Ks[128][36] + Vs[64][68] = 13568 u32 = 54272 B
#define FQ_OFF 0
#define FK_OFF (128*36)
#define FV_OFF (2*128*36)
#define FL_SMEM_BYTES ((2*128*36 + 64*68) * 4)

__global__ void __launch_bounds__(256) flash_kernel(float* __restrict__ attn)
{
    extern __shared__ uint32_t sm[];
    uint32_t (*Qs)[36] = reinterpret_cast<uint32_t(*)[36]>(sm + FQ_OFF);
    uint32_t (*Ks)[36] = reinterpret_cast<uint32_t(*)[36]>(sm + FK_OFF);
    uint32_t (*Vs)[68] = reinterpret_cast<uint32_t(*)[68]>(sm + FV_OFF);

    const int z  = blockIdx.y;
    const int m0 = blockIdx.x * 128;
    const float* __restrict__ Qg  = g_QKV[0] + (size_t)z*SEQ*HD;
    const float* __restrict__ Kg  = g_QKV[1] + (size_t)z*SEQ*HD;
    const float* __restrict__ Vtg = g_Vt     + (size_t)z*HD*SEQ;
    float* __restrict__ Cz = attn + (size_t)z*SEQ*SEQ;

    const int tid = threadIdx.x, lane = tid & 31, warp = tid >> 5;
    const int g = lane >> 2, l = lane & 3;
    const int ra = warp*16 + g;           // this thread's row (and ra+8)

    // ---- stage Q tile once (scaled by SCALE_ATT), packed bf16 ----
#pragma unroll
    for (int it = 0; it < 4; ++it) {
        int idx = tid + it*256;
        int r = idx >> 3, c8 = idx & 7;
        const float* p = &Qg[(size_t)(m0 + r)*HD + c8*8];
        float4 v0 = *reinterpret_cast<const float4*>(p);
        float4 v1 = *reinterpret_cast<const float4*>(p + 4);
        uint4 u = {pbf(v0.x*SCALE_ATT, v0.y*SCALE_ATT), pbf(v0.z*SCALE_ATT, v0.w*SCALE_ATT),
                   pbf(v1.x*SCALE_ATT, v1.y*SCALE_ATT), pbf(v1.z*SCALE_ATT, v1.w*SCALE_ATT)};
        *reinterpret_cast<uint4*>(&Qs[r][c8*4]) = u;
    }

    // prefetch K(0)
    float4 kA[4], kB[4];
#pragma unroll
    for (int it = 0; it < 4; ++it) {
        int idx = tid + it*256;
        int r = idx >> 3, c8 = idx & 7;
        const float* p = &Kg[(size_t)r*HD + c8*8];
        kA[it] = *reinterpret_cast<const float4*>(p);
        kB[it] = *reinterpret_cast<const float4*>(p + 4);
    }

    float M0 = -3.0e38f, M1 = -3.0e38f, S0 = 0.f, S1 = 0.f;

    // ================= pass 1: row max + sumexp (register stats) ==========
    for (int j = 0; j < 16; ++j) {
#pragma unroll
        for (int it = 0; it < 4; ++it) {
            int idx = tid + it*256;
            int r = idx >> 3, c8 = idx & 7;
            uint4 u = {pbf(kA[it].x, kA[it].y), pbf(kA[it].z, kA[it].w),
                       pbf(kB[it].x, kB[it].y), pbf(kB[it].z, kB[it].w)};
            *reinterpret_cast<uint4*>(&Ks[r][c8*4]) = u;
        }
        __syncthreads();
        if (j < 15) {
#pragma unroll
            for (int it = 0; it < 4; ++it) {
                int idx = tid + it*256;
                int r = idx >> 3, c8 = idx & 7;
                const float* p = &Kg[(size_t)((j+1)*128 + r)*HD + c8*8];
                kA[it] = *reinterpret_cast<const float4*>(p);
                kB[it] = *reinterpret_cast<const float4*>(p + 4);
            }
        }

        float cs[16][4];
#pragma unroll
        for (int nt = 0; nt < 16; ++nt)
#pragma unroll
            for (int d = 0; d < 4; ++d) cs[nt][d] = 0.f;

#pragma unroll
        for (int ks = 0; ks < 4; ++ks) {
            const int kk = ks*8 + l;
            uint32_t a0 = Qs[ra][kk],   a1 = Qs[ra+8][kk];
            uint32_t a2 = Qs[ra][kk+4], a3 = Qs[ra+8][kk+4];
#pragma unroll
            for (int nt = 0; nt < 16; ++nt) {
                uint32_t b0 = Ks[nt*8 + g][kk], b1 = Ks[nt*8 + g][kk+4];
                mma_bf16(cs[nt], a0, a1, a2, a3, b0, b1);
            }
        }

        // tile row max (quad shuffles)
        float t0 = -3.0e38f, t1 = -3.0e38f;
#pragma unroll
        for (int nt = 0; nt < 16; ++nt) {
            t0 = fmaxf(t0, fmaxf(cs[nt][0], cs[nt][1]));
            t1 = fmaxf(t1, fmaxf(cs[nt][2], cs[nt][3]));
        }
        t0 = fmaxf(t0, __shfl_xor_sync(0xffffffffu, t0, 1));
        t0 = fmaxf(t0, __shfl_xor_sync(0xffffffffu, t0, 2));
        t1 = fmaxf(t1, __shfl_xor_sync(0xffffffffu, t1, 1));
        t1 = fmaxf(t1, __shfl_xor_sync(0xffffffffu, t1, 2));

        float e0 = 0.f, e1 = 0.f;
#pragma unroll
        for (int nt = 0; nt < 16; ++nt) {
            e0 += __expf(cs[nt][0] - t0) + __expf(cs[nt][1] - t0);
            e1 += __expf(cs[nt][2] - t1) + __expf(cs[nt][3] - t1);
        }
        e0 += __shfl_xor_sync(0xffffffffu, e0, 1);
        e0 += __shfl_xor_sync(0xffffffffu, e0, 2);
        e1 += __shfl_xor_sync(0xffffffffu, e1, 1);
        e1 += __shfl_xor_sync(0xffffffffu, e1, 2);

        float mn0 = fmaxf(M0, t0);
        S0 = S0*__expf(M0 - mn0) + e0*__expf(t0 - mn0);  M0 = mn0;
        float mn1 = fmaxf(M1, t1);
        S1 = S1*__expf(M1 - mn1) + e1*__expf(t1 - mn1);  M1 = mn1;
        __syncthreads();
    }

    const float I0 = 1.0f / S0, I1 = 1.0f / S1;

    float co[8][4];
#pragma unroll
    for (int a = 0; a < 8; ++a)
#pragma unroll
        for (int d = 0; d < 4; ++d) co[a][d] = 0.f;

    // prefetch K(0), V(0) for pass 2
    float4 vA[4], vB[4];
#pragma unroll
    for (int it = 0; it < 4; ++it) {
        int idx = tid + it*256;
        int r = idx >> 3, c8 = idx & 7;
        const float* p = &Kg[(size_t)r*HD + c8*8];
        kA[it] = *reinterpret_cast<const float4*>(p);
        kB[it] = *reinterpret_cast<const float4*>(p + 4);
        int d = idx >> 4, s8 = idx & 15;
        const float* pv = &Vtg[(size_t)d*SEQ + s8*8];
        vA[it] = *reinterpret_cast<const float4*>(pv);
        vB[it] = *reinterpret_cast<const float4*>(pv + 4);
    }

    // ================= pass 2: probs -> attn, P*V -> ctx =================
    for (int j = 0; j < 16; ++j) {
#pragma unroll
        for (int it = 0; it < 4; ++it) {
            int idx = tid + it*256;
            int r = idx >> 3, c8 = idx & 7;
            uint4 u = {pbf(kA[it].x, kA[it].y), pbf(kA[it].z, kA[it].w),
                       pbf(kB[it].x, kB[it].y), pbf(kB[it].z, kB[it].w)};
            *reinterpret_cast<uint4*>(&Ks[r][c8*4]) = u;
            int d = idx >> 4, s8 = idx & 15;
            uint4 uv = {pbf(vA[it].x, vA[it].y), pbf(vA[it].z, vA[it].w),
                        pbf(vB[it].x, vB[it].y), pbf(vB[it].z, vB[it].w)};
            *reinterpret_cast<uint4*>(&Vs[d][s8*4]) = uv;
        }
        __syncthreads();
        if (j < 15) {
#pragma unroll
            for (int it = 0; it < 4; ++it) {
                int idx = tid + it*256;
                int r = idx >> 3, c8 = idx & 7;
                const float* p = &Kg[(size_t)((j+1)*128 + r)*HD + c8*8];
                kA[it] = *reinterpret_cast<const float4*>(p);
                kB[it] = *reinterpret_cast<const float4*>(p + 4);
                int d = idx >> 4, s8 = idx & 15;
                const float* pv = &Vtg[(size_t)d*SEQ + (j+1)*128 + s8*8];
                vA[it] = *reinterpret_cast<const float4*>(pv);
                vB[it] = *reinterpret_cast<const float4*>(pv + 4);
            }
        }

        // recompute S tile
        float cs[16][4];
#pragma unroll
        for (int nt = 0; nt < 16; ++nt)
#pragma unroll
            for (int d = 0; d < 4; ++d) cs[nt][d] = 0.f;
#pragma unroll
        for (int ks = 0; ks < 4; ++ks) {
            const int kk = ks*8 + l;
            uint32_t a0 = Qs[ra][kk],   a1 = Qs[ra+8][kk];
            uint32_t a2 = Qs[ra][kk+4], a3 = Qs[ra+8][kk+4];
#pragma unroll
            for (int nt = 0; nt < 16; ++nt) {
                uint32_t b0 = Ks[nt*8 + g][kk], b1 = Ks[nt*8 + g][kk+4];
                mma_bf16(cs[nt], a0, a1, a2, a3, b0, b1);
            }
        }

        // per 16-col group kg: probs -> attn, same-thread repack, PV MMA
#pragma unroll
        for (int kg = 0; kg < 8; ++kg) {
            float p[2][4];
#pragma unroll
            for (int h2 = 0; h2 < 2; ++h2) {
                int nt = kg*2 + h2;
                p[h2][0] = __expf(cs[nt][0] - M0) * I0;
                p[h2][1] = __expf(cs[nt][1] - M0) * I0;
                p[h2][2] = __expf(cs[nt][2] - M1) * I1;
                p[h2][3] = __expf(cs[nt][3] - M1) * I1;
                int colg = j*128 + nt*8 + 2*l;
                float2 v0 = {p[h2][0], p[h2][1]};
                *reinterpret_cast<float2*>(&Cz[(size_t)(m0 + ra)*SEQ + colg]) = v0;
                float2 v1 = {p[h2][2], p[h2][3]};
                *reinterpret_cast<float2*>(&Cz[(size_t)(m0 + ra + 8)*SEQ + colg]) = v1;
            }
            // C-frag -> bf16 A-frag: pure same-thread repack (no shuffles)
            uint32_t a0 = pbf(p[0][0], p[0][1]);
            uint32_t a1 = pbf(p[0][2], p[0][3]);
            uint32_t a2 = pbf(p[1][0], p[1][1]);
            uint32_t a3 = pbf(p[1][2], p[1][3]);
            const int kk2 = kg*8 + l;
#pragma unroll
            for (int no = 0; no < 8; ++no) {
                uint32_t b0 = Vs[no*8 + g][kk2], b1 = Vs[no*8 + g][kk2+4];
                mma_bf16(co[no], a0, a1, a2, a3, b0, b1);
            }
        }
        __syncthreads();
    }

    // epilogue: context to g_ctx [B,S,HID]
    const int bi = z >> 4, h = z & 15;
#pragma unroll
    for (int no = 0; no < 8; ++no) {
        int d = no*8 + 2*l;
        int q = m0 + ra;
        float2 v0 = {co[no][0], co[no][1]};
        *reinterpret_cast<float2*>(&g_ctx[((size_t)bi*SEQ + q)*HID + (h<<6) + d]) = v0;
        float2 v1 = {co[no][2], co[no][3]};
        *reinterpret_cast<float2*>(&g_ctx[((size_t)bi*SEQ + q + 8)*HID + (h<<6) + d]) = v1;
    }
}

// ---------------- 5) output = ctx @ Wo^T + bo (bf16 mma) ----------------
__global__ void out_mma_kernel(const float* __restrict__ Wo,
                               const float* __restrict__ bo,
                               float* __restrict__ out)
{
    __shared__ uint32_t As[128][20];
    __shared__ uint32_t Bs[128][20];
    const int m0 = blockIdx.y * 128, n0 = blockIdx.x * 128;
    const int tid = threadIdx.x, lane = tid & 31, warp = tid >> 5;
    const int wm = (warp & 1) * 64, wn = (warp >> 1) * 32;
    const int g = lane >> 2, l = lane & 3;

    float c[4][4][4];
#pragma unroll
    for (int a = 0; a < 4; ++a)
#pragma unroll
        for (int b = 0; b < 4; ++b)
#pragma unroll
            for (int d = 0; d < 4; ++d) c[a][b][d] = 0.f;

    for (int k0 = 0; k0 < HID; k0 += 32) {
#pragma unroll
        for (int it = 0; it < 2; ++it) {
            int idx = tid + it*256;
            int r = idx >> 2, c8 = idx & 3;
            const float* pa = &g_ctx[(size_t)(m0 + r)*HID + k0 + c8*8];
            float4 v0 = *reinterpret_cast<const float4*>(pa);
            float4 v1 = *reinterpret_cast<const float4*>(pa + 4);
            uint4 u = {pbf(v0.x, v0.y), pbf(v0.z, v0.w), pbf(v1.x, v1.y), pbf(v1.z, v1.w)};
            *reinterpret_cast<uint4*>(&As[r][c8*4]) = u;
            const float* pb = &Wo[(size_t)(n0 + r)*HID + k0 + c8*8];
            float4 w0 = *reinterpret_cast<const float4*>(pb);
            float4 w1 = *reinterpret_cast<const float4*>(pb + 4);
            uint4 ub = {pbf(w0.x, w0.y), pbf(w0.z, w0.w), pbf(w1.x, w1.y), pbf(w1.z, w1.w)};
            *reinterpret_cast<uint4*>(&Bs[r][c8*4]) = ub;
        }
        __syncthreads();
#pragma unroll
        for (int ks = 0; ks < 2; ++ks) {
            const int kk = ks*8 + l;
            uint32_t af[4][4], bf[4][2];
#pragma unroll
            for (int mt = 0; mt < 4; ++mt) {
                int r = wm + mt*16 + g;
                af[mt][0] = As[r][kk];     af[mt][1] = As[r+8][kk];
                af[mt][2] = As[r][kk+4];   af[mt][3] = As[r+8][kk+4];
            }
#pragma unroll
            for (int nt = 0; nt < 4; ++nt) {
                int n = wn + nt*8 + g;
                bf[nt][0] = Bs[n][kk];     bf[nt][1] = Bs[n][kk+4];
            }
#pragma unroll
            for (int mt = 0; mt < 4; ++mt)
#pragma unroll
                for (int nt = 0; nt < 4; ++nt)
                    mma_bf16(c[mt][nt], af[mt][0], af[mt][1], af[mt][2], af[mt][3],
                             bf[nt][0], bf[nt][1]);
        }
        __syncthreads();
    }
#pragma unroll
    for (int mt = 0; mt < 4; ++mt) {
#pragma unroll
        for (int nt = 0; nt < 4; ++nt) {
            int ncol = n0 + wn + nt*8 + 2*l;
            float b0 = bo[ncol], b1 = bo[ncol+1];
            int mA = m0 + wm + mt*16 + g;
            float2 v0 = {c[mt][nt][0] + b0, c[mt][nt][1] + b1};
            *reinterpret_cast<float2*>(&out[(size_t)mA*HID + ncol]) = v0;
            float2 v1 = {c[mt][nt][2] + b0, c[mt][nt][3] + b1};
            *reinterpret_cast<float2*>(&out[(size_t)(mA+8)*HID + ncol]) = v1;
        }
    }
}

// ---------------- launch ----------------
extern "C" void kernel_launch(void* const* d_in, const int* in_sizes, int n_in,
                              void* d_out, int out_size)
{
    const float* query = (const float*)d_in[0];
    const float* key   = (const float*)d_in[1];
    const float* value = (const float*)d_in[2];
    const float* Wq = (const float*)d_in[3];  const float* bq = (const float*)d_in[4];
    const float* Wk = (const float*)d_in[5];  const float* bk = (const float*)d_in[6];
    const float* Wv = (const float*)d_in[7];  const float* bv = (const float*)d_in[8];
    const float* Wo = (const float*)d_in[9];  const float* bo = (const float*)d_in[10];
    const float* ent_w = (const float*)d_in[11];
    const float* ent_s = (const float*)d_in[12];
    const float* sup_w = (const float*)d_in[13];
    const float* sup_c = (const float*)d_in[14];

    float* out  = (float*)d_out;                 // [B,S,HID]
    float* attn = (float*)d_out + OUT_ELEMS;     // [B,NH,S,S]
    (void)in_sizes; (void)n_in; (void)out_size;

    static bool attr_set = false;
    if (!attr_set) {
        cudaFuncSetAttribute(flash_kernel,
                             cudaFuncAttributeMaxDynamicSharedMemorySize,
                             FL_SMEM_BYTES);
        attr_set = true;
    }

    // 1) composite 64x64 transforms
    build_T_kernel<<<1, 128>>>(ent_w, ent_s, sup_w, sup_c);

    // 2) fold transforms into projection weights (merged)
    transform_W_kernel<<<dim3(16, 16, 3), 256>>>(Wq, bq, Wk, bk, Wv, bv);

    // 3) projections (bf16 mma, merged); V written pre-transposed
    proj_mma_kernel<<<dim3(HID/128, MROWS/128, 3), 256>>>(query, key, value);

    // 4) fused attention: probs -> attn (single write), context -> g_ctx
    flash_kernel<<<dim3(SEQ/128, BH), 256, FL_SMEM_BYTES>>>(attn);

    // 5) output projection (bf16 mma)
    out_mma_kernel<<<dim3(HID/128, MROWS/128), 256>>>(Wo, bo, out);
}

// round 16
// speedup vs baseline: 7.5608x; 1.1361x over previous
#include <cuda_runtime.h>
#include <cuda_bf16.h>
#include <cstdint>
#include <cstddef>

// Problem constants
#define BATCH 2
#define SEQ   2048
#define HID   1024
#define NH    16
#define HD    64
#define BH    (BATCH*NH)            // 32
#define MROWS (BATCH*SEQ)           // 4096
#define SCALE_ATT 0.125f            // 1/sqrt(64)
#define OUT_ELEMS ((size_t)BATCH*SEQ*HID)          // 4,194,304

// ---------------- device scratch (no allocs allowed) ----------------
__device__ float g_T[2][64*64];                 // 0: T for Q/K, 1: T for V
__device__ float g_Wt[3][HID*HID];              // transformed Wq,Wk,Wv
__device__ float g_bt[3][HID];
__device__ __nv_bfloat16 g_Qb[(size_t)BH*SEQ*HD];   // Q (pre-scaled) [bh][s][d]
__device__ __nv_bfloat16 g_Kb[(size_t)BH*SEQ*HD];   // K [bh][s][d]
__device__ __nv_bfloat16 g_Vtb[(size_t)BH*HD*SEQ];  // V transposed [bh][d][s]
__device__ __nv_bfloat16 g_ctxb[(size_t)MROWS*HID]; // context [B,S,HID]

// ---------------- bf16 mma helpers ----------------
__device__ __forceinline__ uint32_t pbf(float lo, float hi) {
    uint32_t r;
    asm("cvt.rn.bf16x2.f32 %0, %1, %2;" : "=r"(r) : "f"(hi), "f"(lo));
    return r;
}
__device__ __forceinline__ void mma_bf16(float c[4],
                                         uint32_t a0, uint32_t a1, uint32_t a2, uint32_t a3,
                                         uint32_t b0, uint32_t b1) {
    asm volatile(
        "mma.sync.aligned.m16n8k16.row.col.f32.bf16.bf16.f32 "
        "{%0,%1,%2,%3}, {%4,%5,%6,%7}, {%8,%9}, {%0,%1,%2,%3};"
        : "+f"(c[0]), "+f"(c[1]), "+f"(c[2]), "+f"(c[3])
        : "r"(a0), "r"(a1), "r"(a2), "r"(a3), "r"(b0), "r"(b1));
}
__device__ __forceinline__ void cpa16(const void* smem_dst, const void* gsrc) {
    uint32_t d = (uint32_t)__cvta_generic_to_shared(smem_dst);
    asm volatile("cp.async.cg.shared.global [%0], [%1], 16;" :: "r"(d), "l"(gsrc));
}
#define CP_COMMIT() asm volatile("cp.async.commit_group;")
#define CP_WAIT1()  asm volatile("cp.async.wait_group 1;")
#define CP_WAIT0()  asm volatile("cp.async.wait_group 0;")

// ---------------- 1) build the 64x64 composite transforms ----------------
__global__ void build_T_kernel(const float* __restrict__ ent_w,  // [4,16,16]
                               const float* __restrict__ ent_s,  // [4]
                               const float* __restrict__ sup_w,  // [8,64]
                               const float* __restrict__ sup_c)  // [8]
{
    int t = threadIdx.x;
    if (t >= 128) return;
    int v = t >> 6;      // 0: QK path, 1: V path
    int i = t & 63;

    float x[64];
#pragma unroll
    for (int j = 0; j < 64; ++j) x[j] = (j == i) ? 1.0f : 0.0f;

    float w[64];
    for (int p = 0; p < 4; ++p)
        for (int j = 0; j < 16; ++j) {
            float acc = 0.f;
            for (int ii = 0; ii < 16; ++ii)
                acc += x[p*16 + ii] * ent_w[p*256 + ii*16 + j];
            w[p*16 + j] = acc;
        }
    for (int g = 0; g < 16; ++g) {
        float sc = ent_s[g >> 2];
        x[4*g+0] = w[4*g+0]*sc;
        x[4*g+1] = w[4*g+1]*sc;
        x[4*g+2] = w[4*g+3]*sc;
        x[4*g+3] = w[4*g+2]*sc;
    }
    const float R = 0.70710678118654752440f;
    for (int pr = 0; pr < 32; ++pr) {
        float a = x[2*pr], b = x[2*pr+1];
        x[2*pr]   = (a + b) * R;
        x[2*pr+1] = (a - b) * R;
    }
    for (int d = 0; d < 64; ++d) {
        float s = 0.f;
        for (int n = 0; n < 8; ++n) s += sup_c[n] * sup_w[n*64 + d];
        x[d] *= s;
    }
    if (v == 0) {
        for (int pr = 0; pr < 32; ++pr) {
            float a = x[2*pr], b = x[2*pr+1];
            x[2*pr]   = (a + b) * R;
            x[2*pr+1] = (a - b) * R;
        }
    } else {
        for (int g = 0; g < 16; ++g) {
            float a = x[4*g+2];
            x[4*g+2] = x[4*g+3];
            x[4*g+3] = a;
        }
    }
#pragma unroll
    for (int j = 0; j < 64; ++j) g_T[v][i*64 + j] = x[j];
}

// ---------------- 2) fold T into projection weights (merged 3 mats) -------
// SCALE_ATT is folded into the Q weights/bias (mat 0).
__global__ void transform_W_kernel(const float* __restrict__ Wq, const float* __restrict__ bq,
                                   const float* __restrict__ Wk, const float* __restrict__ bk,
                                   const float* __restrict__ Wv, const float* __restrict__ bv)
{
    __shared__ float Ts[64][65];
    __shared__ float Ws[64][65];
    const int mat = blockIdx.z;
    const float* __restrict__ W    = (mat == 0) ? Wq : (mat == 1) ? Wk : Wv;
    const float* __restrict__ bvec = (mat == 0) ? bq : (mat == 1) ? bk : bv;
    const float* __restrict__ T = g_T[(mat == 2) ? 1 : 0];
    const float sc = (mat == 0) ? SCALE_ATT : 1.0f;
    const int head = blockIdx.y;
    const int k0 = blockIdx.x * 64;
    const int tid = threadIdx.x;

#pragma unroll
    for (int l = 0; l < 16; ++l) {
        int idx = tid + l*256;
        int i = idx >> 6, c = idx & 63;
        Ts[i][c] = T[idx];
        Ws[i][c] = W[(size_t)(head*64 + i)*HID + k0 + c];
    }
    __syncthreads();

    const int k = tid & 63, g = tid >> 6;   // g in 0..3, 16 ml values each
    float acc[16] = {};
    for (int i = 0; i < 64; ++i) {
        float wv = Ws[i][k];
#pragma unroll
        for (int j = 0; j < 16; ++j)
            acc[j] += Ts[i][g*16 + j] * wv;
    }
#pragma unroll
    for (int j = 0; j < 16; ++j)
        g_Wt[mat][(size_t)(head*64 + g*16 + j)*HID + k0 + k] = acc[j] * sc;

    if (blockIdx.x == 0 && tid < 64) {
        float ab = 0.f;
        for (int i = 0; i < 64; ++i)
            ab += Ts[i][tid] * bvec[head*64 + i];
        g_bt[mat][head*64 + tid] = ab * sc;
    }
}

// ---------------- 3) projections (bf16 mma, merged 3 mats) -----------------
// mat 0 -> g_Qb, mat 1 -> g_Kb (both [bh][s][d]), mat 2 -> g_Vtb [bh][d][s]
__global__ void proj_mma_kernel(const float* __restrict__ Aq,
                                const float* __restrict__ Ak,
                                const float* __restrict__ Av)
{
    __shared__ uint32_t As[128][20];
    __shared__ uint32_t Bs[128][20];
    const int mat = blockIdx.z;
    const float* __restrict__ A  = (mat == 0) ? Aq : (mat == 1) ? Ak : Av;
    const float* __restrict__ Wm = g_Wt[mat];
    const float* __restrict__ bm = g_bt[mat];

    const int m0 = blockIdx.y * 128, n0 = blockIdx.x * 128;
    const int tid = threadIdx.x, lane = tid & 31, warp = tid >> 5;
    const int wm = (warp & 1) * 64, wn = (warp >> 1) * 32;
    const int g = lane >> 2, l = lane & 3;

    float c[4][4][4];
#pragma unroll
    for (int a = 0; a < 4; ++a)
#pragma unroll
        for (int b = 0; b < 4; ++b)
#pragma unroll
            for (int d = 0; d < 4; ++d) c[a][b][d] = 0.f;

    for (int k0 = 0; k0 < HID; k0 += 32) {
#pragma unroll
        for (int it = 0; it < 2; ++it) {
            int idx = tid + it*256;
            int r = idx >> 2, c8 = idx & 3;
            const float* pa = &A[(size_t)(m0 + r)*HID + k0 + c8*8];
            float4 v0 = *reinterpret_cast<const float4*>(pa);
            float4 v1 = *reinterpret_cast<const float4*>(pa + 4);
            uint4 u = {pbf(v0.x, v0.y), pbf(v0.z, v0.w), pbf(v1.x, v1.y), pbf(v1.z, v1.w)};
            *reinterpret_cast<uint4*>(&As[r][c8*4]) = u;
            const float* pb = &Wm[(size_t)(n0 + r)*HID + k0 + c8*8];
            float4 w0 = *reinterpret_cast<const float4*>(pb);
            float4 w1 = *reinterpret_cast<const float4*>(pb + 4);
            uint4 ub = {pbf(w0.x, w0.y), pbf(w0.z, w0.w), pbf(w1.x, w1.y), pbf(w1.z, w1.w)};
            *reinterpret_cast<uint4*>(&Bs[r][c8*4]) = ub;
        }
        __syncthreads();
#pragma unroll
        for (int ks = 0; ks < 2; ++ks) {
            const int kk = ks*8 + l;
            uint32_t af[4][4], bf[4][2];
#pragma unroll
            for (int mt = 0; mt < 4; ++mt) {
                int r = wm + mt*16 + g;
                af[mt][0] = As[r][kk];     af[mt][1] = As[r+8][kk];
                af[mt][2] = As[r][kk+4];   af[mt][3] = As[r+8][kk+4];
            }
#pragma unroll
            for (int nt = 0; nt < 4; ++nt) {
                int n = wn + nt*8 + g;
                bf[nt][0] = Bs[n][kk];     bf[nt][1] = Bs[n][kk+4];
            }
#pragma unroll
            for (int mt = 0; mt < 4; ++mt)
#pragma unroll
                for (int nt = 0; nt < 4; ++nt)
                    mma_bf16(c[mt][nt], af[mt][0], af[mt][1], af[mt][2], af[mt][3],
                             bf[nt][0], bf[nt][1]);
        }
        __syncthreads();
    }
    if (mat == 2) {
        // write V transposed bf16: g_Vtb[(bi*NH+h)*HD + d][s]
#pragma unroll
        for (int mt = 0; mt < 4; ++mt) {
#pragma unroll
            for (int nt = 0; nt < 4; ++nt) {
                int ncol = n0 + wn + nt*8 + 2*l;
                int h = ncol >> 6, d = ncol & 63;
                float b0 = bm[ncol], b1 = bm[ncol+1];
                int mA = m0 + wm + mt*16 + g;
                {
                    int bi = mA >> 11, s = mA & 2047;
                    size_t base = ((size_t)(bi*NH + h)*HD + d)*SEQ + s;
                    g_Vtb[base]       = __float2bfloat16(c[mt][nt][0] + b0);
                    g_Vtb[base + SEQ] = __float2bfloat16(c[mt][nt][1] + b1);
                }
                {
                    int mB = mA + 8;
                    int bi = mB >> 11, s = mB & 2047;
                    size_t base = ((size_t)(bi*NH + h)*HD + d)*SEQ + s;
                    g_Vtb[base]       = __float2bfloat16(c[mt][nt][2] + b0);
                    g_Vtb[base + SEQ] = __float2bfloat16(c[mt][nt][3] + b1);
                }
            }
        }
    } else {
        uint32_t* __restrict__ Cdst =
            reinterpret_cast<uint32_t*>((mat == 0) ? g_Qb : g_Kb);
#pragma unroll
        for (int mt = 0; mt < 4; ++mt) {
#pragma unroll
            for (int nt = 0; nt < 4; ++nt) {
                int ncol = n0 + wn + nt*8 + 2*l;
                int h = ncol >> 6, d = ncol & 63;
                float b0 = bm[ncol], b1 = bm[ncol+1];
                int mA = m0 + wm + mt*16 + g;
                {
                    int bi = mA >> 11, s = mA & 2047;
                    Cdst[((((size_t)bi*NH + h)*SEQ + s)*HD + d) >> 1] =
                        pbf(c[mt][nt][0] + b0, c[mt][nt][1] + b1);
                }
                {
                    int mB = mA + 8;
                    int bi = mB >> 11, s = mB & 2047;
                    Cdst[((((size_t)bi*NH + h)*SEQ + s)*HD + d) >> 1] =
                        pbf(c[mt][nt][2] + b0, c[mt][nt][3] + b1);
                }
            }
        }
    }
}

// ---------------- 4) flash attention, bf16 + cp.async double buffer --------
// grid (SEQ/128=16, BH=32), 256 threads, 2 CTAs/SM target.
// smem (u32): Qs[128][36] | Ks[2][128][36] | Vs[2][64][68]  = 90112 B
#define FQ_OFF 0
#define FK_OFF (128*36)
#define FV_OFF (128*36*3)
#define FL_SMEM_BYTES ((128*36*3 + 2*64*68) * 4)

__global__ void __launch_bounds__(256, 2) flash_kernel(float* __restrict__ attn)
{
    extern __shared__ uint32_t sm[];
    uint32_t (*Qs)[36] = reinterpret_cast<uint32_t(*)[36]>(sm + FQ_OFF);
    uint32_t (*Ks)[128][36] = reinterpret_cast<uint32_t(*)[128][36]>(sm + FK_OFF);
    uint32_t (*Vs)[64][68]  = reinterpret_cast<uint32_t(*)[64][68]>(sm + FV_OFF);

    const int z  = blockIdx.y;
    const int m0 = blockIdx.x * 128;
    const __nv_bfloat16* __restrict__ Qg = g_Qb  + (size_t)z*SEQ*HD + (size_t)m0*HD;
    const __nv_bfloat16* __restrict__ Kg = g_Kb  + (size_t)z*SEQ*HD;
    const __nv_bfloat16* __restrict__ Vg = g_Vtb + (size_t)z*HD*SEQ;
    float* __restrict__ Cz = attn + (size_t)z*SEQ*SEQ;

    const int tid = threadIdx.x, lane = tid & 31, warp = tid >> 5;
    const int g = lane >> 2, l = lane & 3;
    const int ra = warp*16 + g;           // this thread's row (and ra+8)

    const int cr = tid >> 3, cc = (tid & 7) * 8;      // K/Q copy coords (4 iters x 32 rows)
    const int vr = tid >> 4, vc = (tid & 15) * 8;     // V copy coords (4 iters x 16 rows)

    // stage Q (group), then K(0) (group)
#pragma unroll
    for (int it = 0; it < 4; ++it)
        cpa16(&Qs[cr + it*32][cc >> 1], Qg + (size_t)(cr + it*32)*HD + cc);
    CP_COMMIT();
#pragma unroll
    for (int it = 0; it < 4; ++it)
        cpa16(&Ks[0][cr + it*32][cc >> 1], Kg + (size_t)(cr + it*32)*HD + cc);
    CP_COMMIT();

    // Q fragments -> registers (persist across both passes)
    CP_WAIT1();           // Q group done (K0 may be pending)
    __syncthreads();
    uint32_t qf[4][4];
#pragma unroll
    for (int ks = 0; ks < 4; ++ks) {
        const int kk = ks*8 + l;
        qf[ks][0] = Qs[ra][kk];     qf[ks][1] = Qs[ra+8][kk];
        qf[ks][2] = Qs[ra][kk+4];   qf[ks][3] = Qs[ra+8][kk+4];
    }

    float M0 = -3.0e38f, M1 = -3.0e38f, S0 = 0.f, S1 = 0.f;

    // ================= pass 1: row max + sumexp =================
    for (int j = 0; j < 16; ++j) {
        if (j < 15) {
#pragma unroll
            for (int it = 0; it < 4; ++it)
                cpa16(&Ks[(j+1)&1][cr + it*32][cc >> 1],
                      Kg + (size_t)((j+1)*128 + cr + it*32)*HD + cc);
            CP_COMMIT();
            CP_WAIT1();
        } else {
            CP_WAIT0();
        }
        __syncthreads();
        const uint32_t (*Kb)[36] = Ks[j & 1];

#pragma unroll
        for (int half = 0; half < 2; ++half) {
            float cs[8][4];
#pragma unroll
            for (int nt = 0; nt < 8; ++nt)
#pragma unroll
                for (int d = 0; d < 4; ++d) cs[nt][d] = 0.f;
#pragma unroll
            for (int ks = 0; ks < 4; ++ks) {
                const int kk = ks*8 + l;
#pragma unroll
                for (int nt = 0; nt < 8; ++nt) {
                    const uint32_t* row = Kb[half*64 + nt*8 + g];
                    mma_bf16(cs[nt], qf[ks][0], qf[ks][1], qf[ks][2], qf[ks][3],
                             row[kk], row[kk+4]);
                }
            }
            float t0 = -3.0e38f, t1 = -3.0e38f;
#pragma unroll
            for (int nt = 0; nt < 8; ++nt) {
                t0 = fmaxf(t0, fmaxf(cs[nt][0], cs[nt][1]));
                t1 = fmaxf(t1, fmaxf(cs[nt][2], cs[nt][3]));
            }
            t0 = fmaxf(t0, __shfl_xor_sync(0xffffffffu, t0, 1));
            t0 = fmaxf(t0, __shfl_xor_sync(0xffffffffu, t0, 2));
            t1 = fmaxf(t1, __shfl_xor_sync(0xffffffffu, t1, 1));
            t1 = fmaxf(t1, __shfl_xor_sync(0xffffffffu, t1, 2));
            float e0 = 0.f, e1 = 0.f;
#pragma unroll
            for (int nt = 0; nt < 8; ++nt) {
                e0 += __expf(cs[nt][0] - t0) + __expf(cs[nt][1] - t0);
                e1 += __expf(cs[nt][2] - t1) + __expf(cs[nt][3] - t1);
            }
            e0 += __shfl_xor_sync(0xffffffffu, e0, 1);
            e0 += __shfl_xor_sync(0xffffffffu, e0, 2);
            e1 += __shfl_xor_sync(0xffffffffu, e1, 1);
            e1 += __shfl_xor_sync(0xffffffffu, e1, 2);
            float mn0 = fmaxf(M0, t0);
            S0 = S0*__expf(M0 - mn0) + e0*__expf(t0 - mn0);  M0 = mn0;
            float mn1 = fmaxf(M1, t1);
            S1 = S1*__expf(M1 - mn1) + e1*__expf(t1 - mn1);  M1 = mn1;
        }
        __syncthreads();
    }

    const float I0 = 1.0f / S0, I1 = 1.0f / S1;

    float co[8][4];
#pragma unroll
    for (int a = 0; a < 8; ++a)
#pragma unroll
        for (int d = 0; d < 4; ++d) co[a][d] = 0.f;

    // prologue pass 2: K(0)+V(0) one group
#pragma unroll
    for (int it = 0; it < 4; ++it)
        cpa16(&Ks[0][cr + it*32][cc >> 1], Kg + (size_t)(cr + it*32)*HD + cc);
#pragma unroll
    for (int it = 0; it < 4; ++it)
        cpa16(&Vs[0][vr + it*16][vc >> 1], Vg + (size_t)(vr + it*16)*SEQ + vc);
    CP_COMMIT();

    // ================= pass 2: probs -> attn, P*V -> ctx =================
    for (int j = 0; j < 16; ++j) {
        if (j < 15) {
#pragma unroll
            for (int it = 0; it < 4; ++it)
                cpa16(&Ks[(j+1)&1][cr + it*32][cc >> 1],
                      Kg + (size_t)((j+1)*128 + cr + it*32)*HD + cc);
#pragma unroll
            for (int it = 0; it < 4; ++it)
                cpa16(&Vs[(j+1)&1][vr + it*16][vc >> 1],
                      Vg + (size_t)(vr + it*16)*SEQ + (j+1)*128 + vc);
            CP_COMMIT();
            CP_WAIT1();
        } else {
            CP_WAIT0();
        }
        __syncthreads();
        const uint32_t (*Kb)[36] = Ks[j & 1];
        const uint32_t (*Vb)[68] = Vs[j & 1];

#pragma unroll
        for (int half = 0; half < 2; ++half) {
            float cs[8][4];
#pragma unroll
            for (int nt = 0; nt < 8; ++nt)
#pragma unroll
                for (int d = 0; d < 4; ++d) cs[nt][d] = 0.f;
#pragma unroll
            for (int ks = 0; ks < 4; ++ks) {
                const int kk = ks*8 + l;
#pragma unroll
                for (int nt = 0; nt < 8; ++nt) {
                    const uint32_t* row = Kb[half*64 + nt*8 + g];
                    mma_bf16(cs[nt], qf[ks][0], qf[ks][1], qf[ks][2], qf[ks][3],
                             row[kk], row[kk+4]);
                }
            }
            // per 16-col group: probs -> attn, same-thread repack, PV MMA
#pragma unroll
            for (int kg = 0; kg < 4; ++kg) {
                float p[2][4];
#pragma unroll
                for (int h2 = 0; h2 < 2; ++h2) {
                    int nt = kg*2 + h2;
                    p[h2][0] = __expf(cs[nt][0] - M0) * I0;
                    p[h2][1] = __expf(cs[nt][1] - M0) * I0;
                    p[h2][2] = __expf(cs[nt][2] - M1) * I1;
                    p[h2][3] = __expf(cs[nt][3] - M1) * I1;
                    int colg = j*128 + half*64 + nt*8 + 2*l;
                    float2 v0 = {p[h2][0], p[h2][1]};
                    *reinterpret_cast<float2*>(&Cz[(size_t)(m0 + ra)*SEQ + colg]) = v0;
                    float2 v1 = {p[h2][2], p[h2][3]};
                    *reinterpret_cast<float2*>(&Cz[(size_t)(m0 + ra + 8)*SEQ + colg]) = v1;
                }
                uint32_t a0 = pbf(p[0][0], p[0][1]);
                uint32_t a1 = pbf(p[0][2], p[0][3]);
                uint32_t a2 = pbf(p[1][0], p[1][1]);
                uint32_t a3 = pbf(p[1][2], p[1][3]);
                const int kk2 = (half*4 + kg)*8 + l;
#pragma unroll
                for (int no = 0; no < 8; ++no) {
                    const uint32_t* row = Vb[no*8 + g];
                    mma_bf16(co[no], a0, a1, a2, a3, row[kk2], row[kk2+4]);
                }
            }
        }
        __syncthreads();
    }

    // epilogue: context (bf16) to g_ctxb [B,S,HID]
    const int bi = z >> 4, h = z & 15;
    uint32_t* ctxu = reinterpret_cast<uint32_t*>(g_ctxb);
#pragma unroll
    for (int no = 0; no < 8; ++no) {
        int d = no*8 + 2*l;
        int q = m0 + ra;
        ctxu[(((size_t)bi*SEQ + q)*HID + (h<<6) + d) >> 1]     = pbf(co[no][0], co[no][1]);
        ctxu[(((size_t)bi*SEQ + q + 8)*HID + (h<<6) + d) >> 1] = pbf(co[no][2], co[no][3]);
    }
}

// ---------------- 5) output = ctx @ Wo^T + bo (bf16 mma) ----------------
__global__ void out_mma_kernel(const float* __restrict__ Wo,
                               const float* __restrict__ bo,
                               float* __restrict__ out)
{
    __shared__ uint32_t As[128][20];
    __shared__ uint32_t Bs[128][20];
    const int m0 = blockIdx.y * 128, n0 = blockIdx.x * 128;
    const int tid = threadIdx.x, lane = tid & 31, warp = tid >> 5;
    const int wm = (warp & 1) * 64, wn = (warp >> 1) * 32;
    const int g = lane >> 2, l = lane & 3;
    const uint32_t* __restrict__ ctxu = reinterpret_cast<const uint32_t*>(g_ctxb);

    float c[4][4][4];
#pragma unroll
    for (int a = 0; a < 4; ++a)
#pragma unroll
        for (int b = 0; b < 4; ++b)
#pragma unroll
            for (int d = 0; d < 4; ++d) c[a][b][d] = 0.f;

    for (int k0 = 0; k0 < HID; k0 += 32) {
#pragma unroll
        for (int it = 0; it < 2; ++it) {
            int idx = tid + it*256;
            int r = idx >> 2, c8 = idx & 3;
            uint4 u = *reinterpret_cast<const uint4*>(
                &ctxu[((size_t)(m0 + r)*HID + k0) / 2 + c8*4]);
            *reinterpret_cast<uint4*>(&As[r][c8*4]) = u;
            const float* pb = &Wo[(size_t)(n0 + r)*HID + k0 + c8*8];
            float4 w0 = *reinterpret_cast<const float4*>(pb);
            float4 w1 = *reinterpret_cast<const float4*>(pb + 4);
            uint4 ub = {pbf(w0.x, w0.y), pbf(w0.z, w0.w), pbf(w1.x, w1.y), pbf(w1.z, w1.w)};
            *reinterpret_cast<uint4*>(&Bs[r][c8*4]) = ub;
        }
        __syncthreads();
#pragma unroll
        for (int ks = 0; ks < 2; ++ks) {
            const int kk = ks*8 + l;
            uint32_t af[4][4], bf[4][2];
#pragma unroll
            for (int mt = 0; mt < 4; ++mt) {
                int r = wm + mt*16 + g;
                af[mt][0] = As[r][kk];     af[mt][1] = As[r+8][kk];
                af[mt][2] = As[r][kk+4];   af[mt][3] = As[r+8][kk+4];
            }
#pragma unroll
            for (int nt = 0; nt < 4; ++nt) {
                int n = wn + nt*8 + g;
                bf[nt][0] = Bs[n][kk];     bf[nt][1] = Bs[n][kk+4];
            }
#pragma unroll
            for (int mt = 0; mt < 4; ++mt)
#pragma unroll
                for (int nt = 0; nt < 4; ++nt)
                    mma_bf16(c[mt][nt], af[mt][0], af[mt][1], af[mt][2], af[mt][3],
                             bf[nt][0], bf[nt][1]);
        }
        __syncthreads();
    }
#pragma unroll
    for (int mt = 0; mt < 4; ++mt) {
#pragma unroll
        for (int nt = 0; nt < 4; ++nt) {
            int ncol = n0 + wn + nt*8 + 2*l;
            float b0 = bo[ncol], b1 = bo[ncol+1];
            int mA = m0 + wm + mt*16 + g;
            float2 v0 = {c[mt][nt][0] + b0, c[mt][nt][1] + b1};
            *reinterpret_cast<float2*>(&out[(size_t)mA*HID + ncol]) = v0;
            float2 v1 = {c[mt][nt][2] + b0, c[mt][nt][3] + b1};
            *reinterpret_cast<float2*>(&out[(size_t)(mA+8)*HID + ncol]) = v1;
        }
    }
}

// ---------------- launch ----------------
extern "C" void kernel_launch(void* const* d_in, const int* in_sizes, int n_in,
                              void* d_out, int out_size)
{
    const float* query = (const float*)d_in[0];
    const float* key   = (const float*)d_in[1];
    const float* value = (const float*)d_in[2];
    const float* Wq = (const float*)d_in[3];  const float* bq = (const float*)d_in[4];
    const float* Wk = (const float*)d_in[5];  const float* bk = (const float*)d_in[6];
    const float* Wv = (const float*)d_in[7];  const float* bv = (const float*)d_in[8];
    const float* Wo = (const float*)d_in[9];  const float* bo = (const float*)d_in[10];
    const float* ent_w = (const float*)d_in[11];
    const float* ent_s = (const float*)d_in[12];
    const float* sup_w = (const float*)d_in[13];
    const float* sup_c = (const float*)d_in[14];

    float* out  = (float*)d_out;                 // [B,S,HID]
    float* attn = (float*)d_out + OUT_ELEMS;     // [B,NH,S,S]
    (void)in_sizes; (void)n_in; (void)out_size;

    static bool attr_set = false;
    if (!attr_set) {
        cudaFuncSetAttribute(flash_kernel,
                             cudaFuncAttributeMaxDynamicSharedMemorySize,
                             FL_SMEM_BYTES);
        attr_set = true;
    }

    // 1) composite 64x64 transforms
    build_T_kernel<<<1, 128>>>(ent_w, ent_s, sup_w, sup_c);

    // 2) fold transforms into projection weights (merged; Q gets 1/8 scale)
    transform_W_kernel<<<dim3(16, 16, 3), 256>>>(Wq, bq, Wk, bk, Wv, bv);

    // 3) projections (bf16 mma, merged); Q/K bf16, V bf16 pre-transposed
    proj_mma_kernel<<<dim3(HID/128, MROWS/128, 3), 256>>>(query, key, value);

    // 4) fused attention: probs -> attn (single write), context -> g_ctxb
    flash_kernel<<<dim3(SEQ/128, BH), 256, FL_SMEM_BYTES>>>(attn);

    // 5) output projection (bf16 mma)
    out_mma_kernel<<<dim3(HID/128, MROWS/128), 256>>>(Wo, bo, out);
}